// round 9
// baseline (speedup 1.0000x reference)
#include <cuda_runtime.h>
#include <math.h>
#include <stdint.h>

// ---------------- problem constants ----------------
#define DD    768
#define FF    3072
#define NE    8
#define NB    2
#define NL    1024
#define NTOK  2048
#define NH    12
#define HD    64
#define WINW  128
#define NOUT  (NTOK*DD)

// ---------------- device scratch ----------------
__device__ float g_K[NE*NTOK*DD];
__device__ float g_V[NE*NTOK*DD];
__device__ float g_Q[NTOK*DD];
__device__ float g_attn[NTOK*DD];
__device__ float g_Hb[NTOK*FF];
__device__ float g_Y[NTOK*DD];
__device__ float g_xc[NTOK*DD];       // x pre-rounded to tf32 (RN)
__device__ float g_xbar[NB*DD];
__device__ float g_kbar[NE*NB*DD];
__device__ int   g_idx[NTOK];
__device__ int   g_sorted[NTOK];
__device__ int   g_counts[NE];
__device__ int   g_cursor[NE];
__device__ int   g_offs[NE+1];
__device__ float g_Psum[NE];
// transposed + tf32-rounded weights [N][K] per expert
__device__ float g_qT[NE*DD*DD];
__device__ float g_kT[NE*DD*DD];
__device__ float g_vT[NE*DD*DD];
__device__ float g_w1T[NE*DD*FF];
__device__ float g_vgT[NE*DD*FF];
__device__ float g_w2T[NE*FF*DD];
__device__ float g_outT[DD*DD];

// ---------------- PTX helpers (baseline PTX; no sm_103a-suffixed ops) ----------------
__device__ __forceinline__ uint32_t smem_u32(const void* p) {
    uint32_t a;
    asm("{ .reg .u64 t; cvta.to.shared.u64 t, %1; cvt.u32.u64 %0, t; }" : "=r"(a) : "l"(p));
    return a;
}
__device__ __forceinline__ void cp16(uint32_t s, const float* g) {
    asm volatile("cp.async.cg.shared.global [%0], [%1], 16;" :: "r"(s), "l"(g) : "memory");
}
__device__ __forceinline__ void cp_commit() {
    asm volatile("cp.async.commit_group;" ::: "memory");
}
template<int N> __device__ __forceinline__ void cp_wait() {
    asm volatile("cp.async.wait_group %0;" :: "n"(N) : "memory");
}
__device__ __forceinline__ float rntf(float v) {
    uint32_t o;
    asm("cvt.rna.tf32.f32 %0, %1;" : "=r"(o) : "f"(v));
    return __uint_as_float(o);
}
__device__ __forceinline__ void mma8(float* c, const uint32_t* a, const uint32_t* b) {
    asm volatile("mma.sync.aligned.m16n8k8.row.col.f32.tf32.tf32.f32 "
        "{%0,%1,%2,%3}, {%4,%5,%6,%7}, {%8,%9}, {%0,%1,%2,%3};"
        : "+f"(c[0]), "+f"(c[1]), "+f"(c[2]), "+f"(c[3])
        : "r"(a[0]), "r"(a[1]), "r"(a[2]), "r"(a[3]), "r"(b[0]), "r"(b[1]));
}
__device__ __forceinline__ void ldsm4(uint32_t* r, uint32_t addr) {
    asm volatile("ldmatrix.sync.aligned.m8n8.x4.shared.b16 {%0,%1,%2,%3}, [%4];"
        : "=r"(r[0]), "=r"(r[1]), "=r"(r[2]), "=r"(r[3]) : "r"(addr));
}

// ---------------- init / router / offs / scatter ----------------
__global__ void init_k() {
    int t = threadIdx.x;
    if (t < NE) { g_counts[t] = 0; g_Psum[t] = 0.f; }
}

__global__ __launch_bounds__(256) void router_k(const float* __restrict__ x,
                                                const float* __restrict__ gw) {
    int gtid = blockIdx.x * 256 + threadIdx.x;
    int tok  = gtid >> 5;
    int lane = gtid & 31;
    if (tok >= NTOK) return;
    const float* xr = x + (size_t)tok * DD;
    float acc[NE];
#pragma unroll
    for (int e = 0; e < NE; e++) acc[e] = 0.f;
    for (int d = lane; d < DD; d += 32) {
        float xv = xr[d];
        const float* g = gw + (size_t)d * NE;
#pragma unroll
        for (int e = 0; e < NE; e++) acc[e] += xv * g[e];
    }
#pragma unroll
    for (int e = 0; e < NE; e++)
#pragma unroll
        for (int off = 16; off; off >>= 1)
            acc[e] += __shfl_xor_sync(0xffffffffu, acc[e], off);
    if (lane == 0) {
        float l[NE]; float mx = -1e30f;
#pragma unroll
        for (int e = 0; e < NE; e++) { l[e] = acc[e] * 0.5f; mx = fmaxf(mx, l[e]); }
        int best = 0; float bv = l[0];
#pragma unroll
        for (int e = 1; e < NE; e++) if (l[e] > bv) { bv = l[e]; best = e; }
        g_idx[tok] = best;
        atomicAdd(&g_counts[best], 1);
        float p[NE]; float se = 0.f;
#pragma unroll
        for (int e = 0; e < NE; e++) { p[e] = expf(l[e] - mx); se += p[e]; }
        float inv = 1.f / se;
#pragma unroll
        for (int e = 0; e < NE; e++) atomicAdd(&g_Psum[e], p[e] * inv);
    }
}

__global__ void offs_k(float* __restrict__ dout, long long out_size) {
    if (threadIdx.x == 0 && blockIdx.x == 0) {
        int o = 0;
        for (int e = 0; e < NE; e++) { g_offs[e] = o; g_cursor[e] = o; o += g_counts[e]; }
        g_offs[NE] = o;
        float aux = 0.f;
        for (int e = 0; e < NE; e++) aux += (float)g_counts[e] * g_Psum[e];
        aux *= (float)NE / ((float)NTOK * (float)NTOK);
        if (out_size > (long long)NOUT) dout[NOUT] = aux;
    }
}

__global__ void scatter_k() {
    int t = blockIdx.x * 256 + threadIdx.x;
    if (t < NTOK) {
        int e = g_idx[t];
        int p = atomicAdd(&g_cursor[e], 1);
        g_sorted[p] = t;
    }
}

// ---------------- x -> tf32(RN) copy ----------------
__global__ __launch_bounds__(256) void xconv_k(const float* __restrict__ x, float* __restrict__ xc) {
    int i = blockIdx.x * 256 + threadIdx.x;
    if (i < NTOK * DD) xc[i] = rntf(x[i]);
}

// ---------------- x column means per batch ----------------
__global__ __launch_bounds__(256) void xbar_k(const float* __restrict__ x) {
    int b = blockIdx.x;
    for (int d = threadIdx.x; d < DD; d += 256) {
        float s = 0.f;
        const float* xb = x + (size_t)b * NL * DD + d;
        for (int j = 0; j < NL; j++) s += xb[(size_t)j * DD];
        g_xbar[b * DD + d] = s * (1.f / (float)NL);
    }
}

// ---------------- kbar[e,b,:] = xbar[b,:] @ k_w[e] ----------------
__global__ __launch_bounds__(256) void kbar2_k(const float* __restrict__ k_w) {
    int e = blockIdx.x;
    __shared__ float xs[NB * DD];
    for (int i = threadIdx.x; i < NB * DD; i += 256) xs[i] = g_xbar[i];
    __syncthreads();
    const float* W = k_w + (size_t)e * DD * DD;
    for (int d = threadIdx.x; d < DD; d += 256) {
        float a0 = 0.f, a1 = 0.f;
        for (int dk = 0; dk < DD; dk++) {
            float w = W[(size_t)dk * DD + d];
            a0 += xs[dk] * w;
            a1 += xs[DD + dk] * w;
        }
        g_kbar[(e * NB + 0) * DD + d] = a0;
        g_kbar[(e * NB + 1) * DD + d] = a1;
    }
}

// ---------------- weight transpose + tf32 round: src[e][K][N] -> dst[e][N][K] ----------------
__global__ __launch_bounds__(256) void transpose_k(const float* __restrict__ src,
                                                   float* __restrict__ dst, int K, int N) {
    __shared__ float t[32][33];
    const float* s = src + (size_t)blockIdx.z * K * N;
    float* d = dst + (size_t)blockIdx.z * K * N;
    int n0 = blockIdx.x * 32, k0 = blockIdx.y * 32;
    int tx = threadIdx.x, ty = threadIdx.y;
#pragma unroll
    for (int i = 0; i < 32; i += 8)
        t[ty + i][tx] = s[(size_t)(k0 + ty + i) * N + n0 + tx];
    __syncthreads();
#pragma unroll
    for (int i = 0; i < 32; i += 8)
        d[(size_t)(n0 + ty + i) * K + k0 + tx] = rntf(t[tx][ty + i]);
}

// ---------------- slot descriptor for the unified GEMM ----------------
struct Slot {
    const float* B;            // transposed weight base [N][K], row length = K
    float* C;                  // output base
    unsigned long long strideB;  // per-expert stride in B
    unsigned long long strideC;  // per-expert stride in C
    int gather;                // use sorted/offs row map
};

// ---------------- unified tf32 mma.sync GEMM (A and B both via ldmatrix) ----------------
// D[m][n] = sum_k A[m][k] * BT[n][k]
// Block tile 128x128x32, 8 warps (2 m x 4 n), warp tile 64x32, 3-stage cp.async.
// A and B smem tiles: identical 128 rows x 128B, XOR-swizzled, read via ldmatrix.x4.
// BT pre-transposed AND pre-rounded (rna.tf32) -> no cvt, no scalar LDS in mainloop.
// blockIdx.x selects slot (bx/nbx) and n-tile (bx%nbx).
// SWIGLU_EPI: out = silu(z)*acc with z read from zbuf. CVTOUT: round outputs to tf32.
#define ABYTES 16384
#define BBYTES 16384
#define PERSTB ((uint32_t)(ABYTES + BBYTES))
template<bool SWIGLU_EPI, bool CVTOUT>
__global__ __launch_bounds__(256, 2) void gemm1(
    const float* __restrict__ A, int ldc, int K, int nbx,
    Slot s0, Slot s1, Slot s2,
    const int* __restrict__ sorted, const int* __restrict__ offs,
    const float* __restrict__ zbuf)
{
    extern __shared__ float sm[];
    __shared__ int rs[128];
    int which = blockIdx.x / nbx;
    int n0 = (blockIdx.x - which * nbx) * 128;
    const float* Bb; float* Cb; unsigned long long sB, sC; int gat;
    if (which == 0)      { Bb = s0.B; Cb = s0.C; sB = s0.strideB; sC = s0.strideC; gat = s0.gather; }
    else if (which == 1) { Bb = s1.B; Cb = s1.C; sB = s1.strideB; sC = s1.strideC; gat = s1.gather; }
    else                 { Bb = s2.B; Cb = s2.C; sB = s2.strideB; sC = s2.strideC; gat = s2.gather; }
    int e = blockIdx.z;
    int cnt; const int* rmap;
    if (gat) { int st0 = offs[e]; cnt = offs[e + 1] - st0; rmap = sorted + st0; }
    else     { cnt = NTOK; rmap = nullptr; }
    int m0 = blockIdx.y * 128;
    if (m0 >= cnt) return;
    const float* Be = Bb + sB * (size_t)e;
    float* Ce = Cb + sC * (size_t)e;

    int tid = threadIdx.x;
    if (tid < 128) {
        int ra = m0 + tid;
        int row = (ra < cnt) ? ra : (cnt - 1);
        rs[tid] = rmap ? rmap[row] : row;
    }
    __syncthreads();

    uint32_t sbase = smem_u32(sm);

    // per-thread load slots: 4 x 16B for A, 4 x 16B for B (identical layouts)
    const float* aptr[4]; const float* bp[4];
    uint32_t soA[4], soB[4];
#pragma unroll
    for (int i = 0; i < 4; i++) {
        int f = i * 256 + tid;
        int r = f >> 3, c = f & 7;
        aptr[i] = A + (size_t)rs[r] * K + c * 4;
        bp[i]   = Be + (size_t)(n0 + r) * K + c * 4;
        uint32_t so = (uint32_t)(r * 128 + ((c ^ (r & 7)) << 4));
        soA[i]  = sbase + so;
        soB[i]  = sbase + (uint32_t)ABYTES + so;
    }

    int lane = tid & 31, wid = tid >> 5;
    int g = lane >> 2, t4 = lane & 3;
    int wm = wid & 1, wn = wid >> 1;
    int mb0 = wm * 64, nb0 = wn * 32;
    int lr15 = lane & 15;
    int lx = lane & 7, lhi = lane >> 4;

    float c1[4][4][4];
#pragma unroll
    for (int mf = 0; mf < 4; mf++)
#pragma unroll
        for (int nf = 0; nf < 4; nf++)
#pragma unroll
            for (int q = 0; q < 4; q++) c1[mf][nf][q] = 0.f;

    int NIT = K >> 5;

    auto load_tile = [&](int it, int st) {
        uint32_t sb = (uint32_t)st * PERSTB;
        int k0 = it << 5;
#pragma unroll
        for (int i = 0; i < 4; i++) cp16(soA[i] + sb, aptr[i] + k0);
#pragma unroll
        for (int i = 0; i < 4; i++) cp16(soB[i] + sb, bp[i] + k0);
        cp_commit();
    };

    load_tile(0, 0);
    load_tile(1, 1);

    for (int it = 0; it < NIT; it++) {
        if (it == NIT - 1) cp_wait<0>(); else cp_wait<1>();
        __syncthreads();
        int st = it % 3;
        uint32_t Ast = sbase + (uint32_t)st * PERSTB;
        uint32_t Bst = Ast + (uint32_t)ABYTES;

#pragma unroll
        for (int kk = 0; kk < 32; kk += 8) {
            int c0 = kk >> 2;
            uint32_t chs = (uint32_t)(((c0 + lhi) ^ lx) << 4);
            uint32_t af[4][4];
#pragma unroll
            for (int mf = 0; mf < 4; mf++)
                ldsm4(af[mf], Ast + (uint32_t)((mb0 + lr15 + 16 * mf) * 128) + chs);
            uint32_t t0[4], t1[4];
            uint32_t baddr = Bst + (uint32_t)((nb0 + lr15) * 128) + chs;
            ldsm4(t0, baddr);
            ldsm4(t1, baddr + 16 * 128);
            uint32_t bf[4][2];
            bf[0][0] = t0[0]; bf[0][1] = t0[2];
            bf[1][0] = t0[1]; bf[1][1] = t0[3];
            bf[2][0] = t1[0]; bf[2][1] = t1[2];
            bf[3][0] = t1[1]; bf[3][1] = t1[3];
#pragma unroll
            for (int mf = 0; mf < 4; mf++)
#pragma unroll
                for (int nf = 0; nf < 4; nf++)
                    mma8(c1[mf][nf], af[mf], bf[nf]);
        }
        if (it + 2 < NIT) load_tile(it + 2, (it + 2) % 3);
    }

    // ---------------- epilogue ----------------
#pragma unroll
    for (int mf = 0; mf < 4; mf++) {
        int lr0 = mb0 + mf * 16 + g;
        int lr1 = lr0 + 8;
        bool v0 = (m0 + lr0) < cnt;
        bool v1 = (m0 + lr1) < cnt;
        float* p0 = Ce + (size_t)rs[lr0] * ldc + n0 + nb0;
        float* p1 = Ce + (size_t)rs[lr1] * ldc + n0 + nb0;
        const float* z0p = nullptr; const float* z1p = nullptr;
        if (SWIGLU_EPI) {
            z0p = zbuf + (size_t)rs[lr0] * ldc + n0 + nb0;
            z1p = zbuf + (size_t)rs[lr1] * ldc + n0 + nb0;
        }
#pragma unroll
        for (int nf = 0; nf < 4; nf++) {
            int co = nf * 8 + 2 * t4;
            float a0 = c1[mf][nf][0], a1 = c1[mf][nf][1];
            float a2 = c1[mf][nf][2], a3 = c1[mf][nf][3];
            if (SWIGLU_EPI) {
                float2 za = v0 ? *(const float2*)(z0p + co) : make_float2(0.f, 0.f);
                float2 zb = v1 ? *(const float2*)(z1p + co) : make_float2(0.f, 0.f);
                a0 = za.x / (1.f + expf(-za.x)) * a0;
                a1 = za.y / (1.f + expf(-za.y)) * a1;
                a2 = zb.x / (1.f + expf(-zb.x)) * a2;
                a3 = zb.y / (1.f + expf(-zb.y)) * a3;
            }
            if (CVTOUT) { a0 = rntf(a0); a1 = rntf(a1); a2 = rntf(a2); a3 = rntf(a3); }
            if (v0) *(float2*)(p0 + co) = make_float2(a0, a1);
            if (v1) *(float2*)(p1 + co) = make_float2(a2, a3);
        }
    }
}

// ---------------- sliding-window attention with Reynolds modulation ----------------
// KTPAD keeps row stride a multiple of 16 bytes (float4 staging): 772*4=3088.
#define KTPAD 772
__global__ __launch_bounds__(384) void attn_k() {
    int token = blockIdx.x;
    int b = token >> 10;
    int t = token & (NL - 1);
    int e = g_idx[token];

    __shared__ float qs[DD];
    __shared__ float sc[NH][WINW + 4];
    __shared__ float mh[NH], invs[NH];
    __shared__ float ks[16][KTPAD];

    int tid = threadIdx.x, lane = tid & 31, h = tid >> 5;
    for (int d = tid; d < DD; d += 384) qs[d] = g_Q[(size_t)token * DD + d];
    __syncthreads();

    int jlo = (t >= WINW - 1) ? t - (WINW - 1) : 0;
    int nj  = t - jlo + 1;
    size_t ebbase = (size_t)(e * NB + b) * NL * DD;
    const float* Kb = g_K + ebbase;

    // full-row mean via mean key (linearity of dot)
    {
        const float* kb = g_kbar + (size_t)(e * NB + b) * DD + h*64 + lane*2;
        float q0 = qs[h*64 + lane*2], q1 = qs[h*64 + lane*2 + 1];
        float p = q0 * kb[0] + q1 * kb[1];
#pragma unroll
        for (int off = 16; off; off >>= 1) p += __shfl_xor_sync(0xffffffffu, p, off);
        if (lane == 0) mh[h] = p * 0.125f;
    }

    // raw scores over the window, K staged through smem in 16-row tiles
    int j2 = lane >> 1, half = lane & 1;
    const float* qr = &qs[h*64 + half*32];
    int ntile = (nj + 15) >> 4;
    for (int tt = 0; tt < ntile; tt++) {
        int j0 = tt << 4;
        int rows = nj - j0; if (rows > 16) rows = 16;
        for (int v = tid; v < rows * 192; v += 384) {
            int r = v / 192, c4 = v % 192;
            *(float4*)&ks[r][c4 * 4] = *(const float4*)(Kb + (size_t)(jlo + j0 + r) * DD + c4 * 4);
        }
        __syncthreads();
        const float* kr = &ks[j2][h*64 + half*32];
        float s = 0.f;
#pragma unroll
        for (int i = 0; i < 32; i++) s += qr[i] * kr[i];
        s += __shfl_xor_sync(0xffffffffu, s, 1);
        if (half == 0 && j2 < rows) sc[h][j0 + j2] = s * 0.125f;
        __syncthreads();
    }

    // Reynolds modulation + softmax over valid window
    float m = mh[h];
    float mx = -1e30f;
    for (int jj = lane; jj < nj; jj += 32) {
        float sv = sc[h][jj];
        float sig = 1.f / (1.f + __expf(-sv));
        float sp = sv + 0.1f * sv - 0.1f * sig * sig - 0.1f * fabsf(sv - m);
        sc[h][jj] = sp;
        mx = fmaxf(mx, sp);
    }
#pragma unroll
    for (int off = 16; off; off >>= 1) mx = fmaxf(mx, __shfl_xor_sync(0xffffffffu, mx, off));
    float sum = 0.f;
    for (int jj = lane; jj < nj; jj += 32) {
        float pexp = __expf(sc[h][jj] - mx);
        sc[h][jj] = pexp;
        sum += pexp;
    }
#pragma unroll
    for (int off = 16; off; off >>= 1) sum += __shfl_xor_sync(0xffffffffu, sum, off);
    if (lane == 0) invs[h] = 1.f / sum;
    __syncthreads();

    // out = attn @ V (coalesced over d, 4-way j unroll)
    const float* Vb = g_V + ebbase;
    for (int od = tid; od < DD; od += 384) {
        int hh = od >> 6;
        const float* vb = Vb + (size_t)jlo * DD + od;
        float a0 = 0.f, a1 = 0.f, a2 = 0.f, a3 = 0.f;
        int j = 0;
        for (; j + 4 <= nj; j += 4) {
            a0 += sc[hh][j+0] * vb[(size_t)(j+0)*DD];
            a1 += sc[hh][j+1] * vb[(size_t)(j+1)*DD];
            a2 += sc[hh][j+2] * vb[(size_t)(j+2)*DD];
            a3 += sc[hh][j+3] * vb[(size_t)(j+3)*DD];
        }
        for (; j < nj; j++) a0 += sc[hh][j] * vb[(size_t)j*DD];
        g_attn[(size_t)token * DD + od] = rntf((a0 + a1 + a2 + a3) * invs[hh]);
    }
}

// ---------------- launch ----------------
extern "C" void kernel_launch(void* const* d_in, const int* in_sizes, int n_in,
                              void* d_out, int out_size) {
    const float* x      = (const float*)d_in[0];
    const float* gate_w = (const float*)d_in[1];
    const float* q_w    = (const float*)d_in[2];
    const float* k_w    = (const float*)d_in[3];
    const float* v_w    = (const float*)d_in[4];
    const float* w1     = (const float*)d_in[5];
    const float* vg     = (const float*)d_in[6];
    const float* w2     = (const float*)d_in[7];
    const float* out_w  = (const float*)d_in[8];
    float* out = (float*)d_out;

    void *pK, *pV, *pQ, *pA, *pH, *pY, *pXC, *pS, *pO;
    void *pqT, *pkT, *pvT, *pw1T, *pvgT, *pw2T, *poT;
    cudaGetSymbolAddress(&pK, g_K);
    cudaGetSymbolAddress(&pV, g_V);
    cudaGetSymbolAddress(&pQ, g_Q);
    cudaGetSymbolAddress(&pA, g_attn);
    cudaGetSymbolAddress(&pH, g_Hb);
    cudaGetSymbolAddress(&pY, g_Y);
    cudaGetSymbolAddress(&pXC, g_xc);
    cudaGetSymbolAddress(&pS, g_sorted);
    cudaGetSymbolAddress(&pO, g_offs);
    cudaGetSymbolAddress(&pqT, g_qT);
    cudaGetSymbolAddress(&pkT, g_kT);
    cudaGetSymbolAddress(&pvT, g_vT);
    cudaGetSymbolAddress(&pw1T, g_w1T);
    cudaGetSymbolAddress(&pvgT, g_vgT);
    cudaGetSymbolAddress(&pw2T, g_w2T);
    cudaGetSymbolAddress(&poT, g_outT);
    const int* sortedp = (const int*)pS;
    const int* offsp   = (const int*)pO;
    const float* xc = (const float*)pXC;

    const int SM_B = 3 * (ABYTES + BBYTES);   // 98304 B
    cudaFuncSetAttribute(gemm1<false,false>, cudaFuncAttributeMaxDynamicSharedMemorySize, SM_B);
    cudaFuncSetAttribute(gemm1<false,true >, cudaFuncAttributeMaxDynamicSharedMemorySize, SM_B);
    cudaFuncSetAttribute(gemm1<true, true >, cudaFuncAttributeMaxDynamicSharedMemorySize, SM_B);

    // weight transposes (+tf32 RNA round) -> [N][K]
    transpose_k<<<dim3(24, 24, NE), dim3(32, 8)>>>(q_w,   (float*)pqT,  DD, DD);
    transpose_k<<<dim3(24, 24, NE), dim3(32, 8)>>>(k_w,   (float*)pkT,  DD, DD);
    transpose_k<<<dim3(24, 24, NE), dim3(32, 8)>>>(v_w,   (float*)pvT,  DD, DD);
    transpose_k<<<dim3(96, 24, NE), dim3(32, 8)>>>(w1,    (float*)pw1T, DD, FF);
    transpose_k<<<dim3(96, 24, NE), dim3(32, 8)>>>(vg,    (float*)pvgT, DD, FF);
    transpose_k<<<dim3(24, 96, NE), dim3(32, 8)>>>(w2,    (float*)pw2T, FF, DD);
    transpose_k<<<dim3(24, 24, 1),  dim3(32, 8)>>>(out_w, (float*)poT,  DD, DD);

    xconv_k<<<(NTOK * DD) / 256, 256>>>(x, (float*)pXC);
    init_k<<<1, 32>>>();
    router_k<<<NTOK / 8, 256>>>(x, gate_w);
    offs_k<<<1, 32>>>(out, (long long)out_size);
    scatter_k<<<NTOK / 256, 256>>>();
    xbar_k<<<NB, 256>>>(x);
    kbar2_k<<<NE, 256>>>(k_w);

    Slot sK  = { (const float*)pkT,  (float*)pK, (unsigned long long)DD*DD, (unsigned long long)NTOK*DD, 0 };
    Slot sV  = { (const float*)pvT,  (float*)pV, (unsigned long long)DD*DD, (unsigned long long)NTOK*DD, 0 };
    Slot sQ  = { (const float*)pqT,  (float*)pQ, (unsigned long long)DD*DD, 0ull, 1 };
    Slot sW1 = { (const float*)pw1T, (float*)pH, (unsigned long long)DD*FF, 0ull, 1 };
    Slot sVG = { (const float*)pvgT, (float*)pH, (unsigned long long)DD*FF, 0ull, 1 };
    Slot sW2 = { (const float*)pw2T, (float*)pY, (unsigned long long)FF*DD, 0ull, 1 };
    Slot sOW = { (const float*)poT,  out, 0ull, 0ull, 0 };

    // K, V (dense) and Q (gathered) in ONE launch: slot = blockIdx.x / 6
    gemm1<false,false><<<dim3(18, 16, 8), 256, SM_B>>>(
        xc, DD, DD, 6, sK, sV, sQ, sortedp, offsp, nullptr);

    attn_k<<<NTOK, 384>>>();

    // SwiGLU: z = attn @ w1 (raw), then h = silu(z) * (attn @ vg), in-place on g_Hb
    gemm1<false,false><<<dim3(24, 16, 8), 256, SM_B>>>(
        (const float*)pA, FF, DD, 24, sW1, sW1, sW1, sortedp, offsp, nullptr);
    gemm1<true,true><<<dim3(24, 16, 8), 256, SM_B>>>(
        (const float*)pA, FF, DD, 24, sVG, sVG, sVG, sortedp, offsp, (const float*)pH);

    // down projection (gathered, K=3072)
    gemm1<false,true><<<dim3(6, 16, 8), 256, SM_B>>>(
        (const float*)pH, DD, FF, 6, sW2, sW2, sW2, sortedp, offsp, nullptr);

    // final output projection (dense) -> d_out
    gemm1<false,false><<<dim3(6, 16, 1), 256, SM_B>>>(
        (const float*)pY, DD, DD, 6, sOW, sOW, sOW, sortedp, offsp, nullptr);
}

// round 11
// speedup vs baseline: 1.2614x; 1.2614x over previous
#include <cuda_runtime.h>
#include <cuda_fp16.h>
#include <math.h>
#include <stdint.h>

// ---------------- problem constants ----------------
#define DD    768
#define FF    3072
#define NE    8
#define NB    2
#define NL    1024
#define NTOK  2048
#define NH    12
#define HD    64
#define WINW  128
#define NOUT  (NTOK*DD)

// ---------------- device scratch ----------------
__device__ float  g_K[NE*NTOK*DD];
__device__ float  g_V[NE*NTOK*DD];
__device__ float  g_Q[NTOK*DD];
__device__ float  g_Hb[NTOK*FF];          // z (fp32) for SwiGLU
__device__ __half g_xh[NTOK*DD];          // x in fp16 (RN)
__device__ __half g_attnh[NTOK*DD];       // attention output in fp16
__device__ __half g_Hh[NTOK*FF];          // silu(z)*gate in fp16
__device__ __half g_Yh[NTOK*DD];          // down-proj output in fp16
__device__ float  g_xbar[NB*DD];
__device__ float  g_kbar[NE*NB*DD];
__device__ int    g_idx[NTOK];
__device__ int    g_sorted[NTOK];
__device__ int    g_counts[NE];
__device__ int    g_cursor[NE];
__device__ int    g_offs[NE+1];
__device__ float  g_Psum[NE];
// transposed fp16 weights [N][K] per expert
__device__ __half g_qT[NE*DD*DD];
__device__ __half g_kT[NE*DD*DD];
__device__ __half g_vT[NE*DD*DD];
__device__ __half g_w1T[NE*DD*FF];
__device__ __half g_vgT[NE*DD*FF];
__device__ __half g_w2T[NE*FF*DD];
__device__ __half g_outT[DD*DD];

// ---------------- PTX helpers ----------------
__device__ __forceinline__ uint32_t smem_u32(const void* p) {
    uint32_t a;
    asm("{ .reg .u64 t; cvta.to.shared.u64 t, %1; cvt.u32.u64 %0, t; }" : "=r"(a) : "l"(p));
    return a;
}
__device__ __forceinline__ void cp16(uint32_t s, const void* g) {
    asm volatile("cp.async.cg.shared.global [%0], [%1], 16;" :: "r"(s), "l"(g) : "memory");
}
__device__ __forceinline__ void cp_commit() {
    asm volatile("cp.async.commit_group;" ::: "memory");
}
template<int N> __device__ __forceinline__ void cp_wait() {
    asm volatile("cp.async.wait_group %0;" :: "n"(N) : "memory");
}
__device__ __forceinline__ void mma16(float* c, const uint32_t* a, const uint32_t* b) {
    asm volatile("mma.sync.aligned.m16n8k16.row.col.f32.f16.f16.f32 "
        "{%0,%1,%2,%3}, {%4,%5,%6,%7}, {%8,%9}, {%0,%1,%2,%3};"
        : "+f"(c[0]), "+f"(c[1]), "+f"(c[2]), "+f"(c[3])
        : "r"(a[0]), "r"(a[1]), "r"(a[2]), "r"(a[3]), "r"(b[0]), "r"(b[1]));
}
__device__ __forceinline__ void ldsm4(uint32_t* r, uint32_t addr) {
    asm volatile("ldmatrix.sync.aligned.m8n8.x4.shared.b16 {%0,%1,%2,%3}, [%4];"
        : "=r"(r[0]), "=r"(r[1]), "=r"(r[2]), "=r"(r[3]) : "r"(addr));
}

// ---------------- init / router / offs / scatter ----------------
__global__ void init_k() {
    int t = threadIdx.x;
    if (t < NE) { g_counts[t] = 0; g_Psum[t] = 0.f; }
}

__global__ __launch_bounds__(256) void router_k(const float* __restrict__ x,
                                                const float* __restrict__ gw) {
    int gtid = blockIdx.x * 256 + threadIdx.x;
    int tok  = gtid >> 5;
    int lane = gtid & 31;
    if (tok >= NTOK) return;
    const float* xr = x + (size_t)tok * DD;
    float acc[NE];
#pragma unroll
    for (int e = 0; e < NE; e++) acc[e] = 0.f;
    for (int d = lane; d < DD; d += 32) {
        float xv = xr[d];
        const float* g = gw + (size_t)d * NE;
#pragma unroll
        for (int e = 0; e < NE; e++) acc[e] += xv * g[e];
    }
#pragma unroll
    for (int e = 0; e < NE; e++)
#pragma unroll
        for (int off = 16; off; off >>= 1)
            acc[e] += __shfl_xor_sync(0xffffffffu, acc[e], off);
    if (lane == 0) {
        float l[NE]; float mx = -1e30f;
#pragma unroll
        for (int e = 0; e < NE; e++) { l[e] = acc[e] * 0.5f; mx = fmaxf(mx, l[e]); }
        int best = 0; float bv = l[0];
#pragma unroll
        for (int e = 1; e < NE; e++) if (l[e] > bv) { bv = l[e]; best = e; }
        g_idx[tok] = best;
        atomicAdd(&g_counts[best], 1);
        float p[NE]; float se = 0.f;
#pragma unroll
        for (int e = 0; e < NE; e++) { p[e] = expf(l[e] - mx); se += p[e]; }
        float inv = 1.f / se;
#pragma unroll
        for (int e = 0; e < NE; e++) atomicAdd(&g_Psum[e], p[e] * inv);
    }
}

__global__ void offs_k(float* __restrict__ dout, long long out_size) {
    if (threadIdx.x == 0 && blockIdx.x == 0) {
        int o = 0;
        for (int e = 0; e < NE; e++) { g_offs[e] = o; g_cursor[e] = o; o += g_counts[e]; }
        g_offs[NE] = o;
        float aux = 0.f;
        for (int e = 0; e < NE; e++) aux += (float)g_counts[e] * g_Psum[e];
        aux *= (float)NE / ((float)NTOK * (float)NTOK);
        if (out_size > (long long)NOUT) dout[NOUT] = aux;
    }
}

__global__ void scatter_k() {
    int t = blockIdx.x * 256 + threadIdx.x;
    if (t < NTOK) {
        int e = g_idx[t];
        int p = atomicAdd(&g_cursor[e], 1);
        g_sorted[p] = t;
    }
}

// ---------------- x -> fp16 copy ----------------
__global__ __launch_bounds__(256) void xconvh_k(const float* __restrict__ x, __half* __restrict__ xh) {
    int i = blockIdx.x * 256 + threadIdx.x;
    if (i < NTOK * DD) xh[i] = __float2half_rn(x[i]);
}

// ---------------- x column means per batch ----------------
__global__ __launch_bounds__(256) void xbar_k(const float* __restrict__ x) {
    int b = blockIdx.x;
    for (int d = threadIdx.x; d < DD; d += 256) {
        float s = 0.f;
        const float* xb = x + (size_t)b * NL * DD + d;
        for (int j = 0; j < NL; j++) s += xb[(size_t)j * DD];
        g_xbar[b * DD + d] = s * (1.f / (float)NL);
    }
}

// ---------------- kbar[e,b,:] = xbar[b,:] @ k_w[e] ----------------
__global__ __launch_bounds__(256) void kbar2_k(const float* __restrict__ k_w) {
    int e = blockIdx.x;
    __shared__ float xs[NB * DD];
    for (int i = threadIdx.x; i < NB * DD; i += 256) xs[i] = g_xbar[i];
    __syncthreads();
    const float* W = k_w + (size_t)e * DD * DD;
    for (int d = threadIdx.x; d < DD; d += 256) {
        float a0 = 0.f, a1 = 0.f;
        for (int dk = 0; dk < DD; dk++) {
            float w = W[(size_t)dk * DD + d];
            a0 += xs[dk] * w;
            a1 += xs[DD + dk] * w;
        }
        g_kbar[(e * NB + 0) * DD + d] = a0;
        g_kbar[(e * NB + 1) * DD + d] = a1;
    }
}

// ---------------- weight transpose + fp16 convert: src[e][K][N] -> dst[e][N][K] half ----------------
__global__ __launch_bounds__(256) void transposeh_k(const float* __restrict__ src,
                                                    __half* __restrict__ dst, int K, int N) {
    __shared__ float t[32][33];
    const float* s = src + (size_t)blockIdx.z * K * N;
    __half* d = dst + (size_t)blockIdx.z * K * N;
    int n0 = blockIdx.x * 32, k0 = blockIdx.y * 32;
    int tx = threadIdx.x, ty = threadIdx.y;
#pragma unroll
    for (int i = 0; i < 32; i += 8)
        t[ty + i][tx] = s[(size_t)(k0 + ty + i) * N + n0 + tx];
    __syncthreads();
#pragma unroll
    for (int i = 0; i < 32; i += 8)
        d[(size_t)(n0 + ty + i) * K + k0 + tx] = __float2half_rn(t[tx][ty + i]);
}

// ---------------- slot descriptor ----------------
struct SlotH {
    const __half* B;            // transposed half weight [N][K]
    void* C;                    // fp32 or fp16 output base (per OUTHALF)
    unsigned long long strideB;
    unsigned long long strideC;
    int gather;
};

// ---------------- fp16 mma.sync GEMM (m16n8k16, 2x tf32 rate) ----------------
// D[m][n] = sum_k A[m][k] * BT[n][k], fp32 accumulate.
// Block tile 128x128x32, 8 warps (2m x 4n), warp tile 64x32, 4-stage cp.async.
// A/B smem tiles: 128 rows x 80B (64B data + 16B pad) -> ldmatrix conflict-free.
// OUTHALF: store __half C. SWIGLU_EPI: out = silu(z)*acc, z from fp32 zbuf.
#define STG_A  10240
#define STG_AB 20480
template<bool OUTHALF, bool SWIGLU_EPI>
__global__ __launch_bounds__(256, 2) void gemm_h(
    const __half* __restrict__ A, int ldc, int K, int nbx,
    SlotH s0, SlotH s1, SlotH s2,
    const int* __restrict__ sorted, const int* __restrict__ offs,
    const float* __restrict__ zbuf)
{
    extern __shared__ char smc[];
    __shared__ int rs[128];
    int which = blockIdx.x / nbx;
    int n0 = (blockIdx.x - which * nbx) * 128;
    const __half* Bb; void* Cb; unsigned long long sB, sC; int gat;
    if (which == 0)      { Bb = s0.B; Cb = s0.C; sB = s0.strideB; sC = s0.strideC; gat = s0.gather; }
    else if (which == 1) { Bb = s1.B; Cb = s1.C; sB = s1.strideB; sC = s1.strideC; gat = s1.gather; }
    else                 { Bb = s2.B; Cb = s2.C; sB = s2.strideB; sC = s2.strideC; gat = s2.gather; }
    int e = blockIdx.z;
    int cnt; const int* rmap;
    if (gat) { int st0 = offs[e]; cnt = offs[e + 1] - st0; rmap = sorted + st0; }
    else     { cnt = NTOK; rmap = nullptr; }
    int m0 = blockIdx.y * 128;
    if (m0 >= cnt) return;
    const __half* Be = Bb + sB * (size_t)e;

    int tid = threadIdx.x;
    if (tid < 128) {
        int ra = m0 + tid;
        int row = (ra < cnt) ? ra : (cnt - 1);
        rs[tid] = rmap ? rmap[row] : row;
    }
    __syncthreads();

    uint32_t sbase = smem_u32(smc);

    // per-thread load slots: 2 x 16B for A, 2 x 16B for B
    const __half* aptr[2]; const __half* bptr[2];
    uint32_t soA[2], soB[2];
#pragma unroll
    for (int i = 0; i < 2; i++) {
        int f = i * 256 + tid;
        int row = f >> 2, c = f & 3;                  // 4 x 16B chunks per 64B row
        aptr[i] = A + (size_t)rs[row] * K + c * 8;    // halves
        bptr[i] = Be + (size_t)(n0 + row) * K + c * 8;
        uint32_t so = (uint32_t)(row * 80 + c * 16);
        soA[i] = sbase + so;
        soB[i] = sbase + (uint32_t)STG_A + so;
    }

    int lane = tid & 31, wid = tid >> 5;
    int g = lane >> 2, t4 = lane & 3;
    int wm = wid & 1, wn = wid >> 1;
    int mb0 = wm * 64, nb0 = wn * 32;
    int lr = lane & 7, lg = lane >> 3;

    float c1[4][4][4];
#pragma unroll
    for (int mf = 0; mf < 4; mf++)
#pragma unroll
        for (int nf = 0; nf < 4; nf++)
#pragma unroll
            for (int q = 0; q < 4; q++) c1[mf][nf][q] = 0.f;

    int NIT = K >> 5;

    auto load_tile = [&](int it, int st) {
        uint32_t sb = (uint32_t)st * STG_AB;
        int k0 = it << 5;   // halves
#pragma unroll
        for (int i = 0; i < 2; i++) cp16(soA[i] + sb, aptr[i] + k0);
#pragma unroll
        for (int i = 0; i < 2; i++) cp16(soB[i] + sb, bptr[i] + k0);
        cp_commit();
    };

    load_tile(0, 0);
    load_tile(1, 1);
    load_tile(2, 2);

    // A frag address parts (constant over iters)
    uint32_t aRowOff = (uint32_t)((lr + (lg & 1) * 8) * 80 + (lg >> 1) * 16);
    uint32_t bRowOff = (uint32_t)((lr + (lg >> 1) * 8) * 80 + (lg & 1) * 16);

    for (int it = 0; it < NIT; it++) {
        int rem = NIT - 1 - it;
        if (rem >= 2) cp_wait<2>(); else if (rem == 1) cp_wait<1>(); else cp_wait<0>();
        __syncthreads();
        int st = it & 3;
        uint32_t Ast = sbase + (uint32_t)st * STG_AB;
        uint32_t Bst = Ast + (uint32_t)STG_A;

#pragma unroll
        for (int kk = 0; kk < 32; kk += 16) {
            uint32_t kbyte = (uint32_t)(kk * 2);
            uint32_t af[4][4];
#pragma unroll
            for (int mf = 0; mf < 4; mf++)
                ldsm4(af[mf], Ast + (uint32_t)((mb0 + mf * 16) * 80) + aRowOff + kbyte);
            uint32_t bf[2][4];
#pragma unroll
            for (int np = 0; np < 2; np++)
                ldsm4(bf[np], Bst + (uint32_t)((nb0 + np * 16) * 80) + bRowOff + kbyte);
#pragma unroll
            for (int mf = 0; mf < 4; mf++)
#pragma unroll
                for (int nf = 0; nf < 4; nf++)
                    mma16(c1[mf][nf], af[mf], &bf[nf >> 1][(nf & 1) * 2]);
        }
        if (it + 3 < NIT) load_tile(it + 3, (it + 3) & 3);
    }

    // ---------------- epilogue ----------------
#pragma unroll
    for (int mf = 0; mf < 4; mf++) {
        int lr0 = mb0 + mf * 16 + g;
        int lr1 = lr0 + 8;
        bool v0 = (m0 + lr0) < cnt;
        bool v1 = (m0 + lr1) < cnt;
        size_t o0 = (size_t)rs[lr0] * ldc + n0 + nb0;
        size_t o1 = (size_t)rs[lr1] * ldc + n0 + nb0;
#pragma unroll
        for (int nf = 0; nf < 4; nf++) {
            int co = nf * 8 + 2 * t4;
            float a0 = c1[mf][nf][0], a1 = c1[mf][nf][1];
            float a2 = c1[mf][nf][2], a3 = c1[mf][nf][3];
            if (SWIGLU_EPI) {
                float2 za = v0 ? *(const float2*)(zbuf + o0 + co) : make_float2(0.f, 0.f);
                float2 zb = v1 ? *(const float2*)(zbuf + o1 + co) : make_float2(0.f, 0.f);
                a0 = za.x / (1.f + expf(-za.x)) * a0;
                a1 = za.y / (1.f + expf(-za.y)) * a1;
                a2 = zb.x / (1.f + expf(-zb.x)) * a2;
                a3 = zb.y / (1.f + expf(-zb.y)) * a3;
            }
            if (OUTHALF) {
                __half* C = (__half*)Cb + sC * (size_t)e;
                if (v0) *(__half2*)(C + o0 + co) = __floats2half2_rn(a0, a1);
                if (v1) *(__half2*)(C + o1 + co) = __floats2half2_rn(a2, a3);
            } else {
                float* C = (float*)Cb + sC * (size_t)e;
                if (v0) *(float2*)(C + o0 + co) = make_float2(a0, a1);
                if (v1) *(float2*)(C + o1 + co) = make_float2(a2, a3);
            }
        }
    }
}

// ---------------- sliding-window attention with Reynolds modulation ----------------
#define KTPAD 772
__global__ __launch_bounds__(384) void attn_k() {
    int token = blockIdx.x;
    int b = token >> 10;
    int t = token & (NL - 1);
    int e = g_idx[token];

    __shared__ float qs[DD];
    __shared__ float sc[NH][WINW + 4];
    __shared__ float mh[NH], invs[NH];
    __shared__ float ks[16][KTPAD];

    int tid = threadIdx.x, lane = tid & 31, h = tid >> 5;
    for (int d = tid; d < DD; d += 384) qs[d] = g_Q[(size_t)token * DD + d];
    __syncthreads();

    int jlo = (t >= WINW - 1) ? t - (WINW - 1) : 0;
    int nj  = t - jlo + 1;
    size_t ebbase = (size_t)(e * NB + b) * NL * DD;
    const float* Kb = g_K + ebbase;

    // full-row mean via mean key
    {
        const float* kb = g_kbar + (size_t)(e * NB + b) * DD + h*64 + lane*2;
        float q0 = qs[h*64 + lane*2], q1 = qs[h*64 + lane*2 + 1];
        float p = q0 * kb[0] + q1 * kb[1];
#pragma unroll
        for (int off = 16; off; off >>= 1) p += __shfl_xor_sync(0xffffffffu, p, off);
        if (lane == 0) mh[h] = p * 0.125f;
    }

    // raw scores; K staged through smem in 16-row tiles
    int j2 = lane >> 1, half = lane & 1;
    const float* qr = &qs[h*64 + half*32];
    int ntile = (nj + 15) >> 4;
    for (int tt = 0; tt < ntile; tt++) {
        int j0 = tt << 4;
        int rows = nj - j0; if (rows > 16) rows = 16;
        for (int v = tid; v < rows * 192; v += 384) {
            int r = v / 192, c4 = v % 192;
            *(float4*)&ks[r][c4 * 4] = *(const float4*)(Kb + (size_t)(jlo + j0 + r) * DD + c4 * 4);
        }
        __syncthreads();
        const float* kr = &ks[j2][h*64 + half*32];
        float s = 0.f;
#pragma unroll
        for (int i = 0; i < 32; i++) s += qr[i] * kr[i];
        s += __shfl_xor_sync(0xffffffffu, s, 1);
        if (half == 0 && j2 < rows) sc[h][j0 + j2] = s * 0.125f;
        __syncthreads();
    }

    // Reynolds modulation + softmax
    float m = mh[h];
    float mx = -1e30f;
    for (int jj = lane; jj < nj; jj += 32) {
        float sv = sc[h][jj];
        float sig = 1.f / (1.f + __expf(-sv));
        float sp = sv + 0.1f * sv - 0.1f * sig * sig - 0.1f * fabsf(sv - m);
        sc[h][jj] = sp;
        mx = fmaxf(mx, sp);
    }
#pragma unroll
    for (int off = 16; off; off >>= 1) mx = fmaxf(mx, __shfl_xor_sync(0xffffffffu, mx, off));
    float sum = 0.f;
    for (int jj = lane; jj < nj; jj += 32) {
        float pexp = __expf(sc[h][jj] - mx);
        sc[h][jj] = pexp;
        sum += pexp;
    }
#pragma unroll
    for (int off = 16; off; off >>= 1) sum += __shfl_xor_sync(0xffffffffu, sum, off);
    if (lane == 0) invs[h] = 1.f / sum;
    __syncthreads();

    // out = attn @ V -> fp16
    const float* Vb = g_V + ebbase;
    for (int od = tid; od < DD; od += 384) {
        int hh = od >> 6;
        const float* vb = Vb + (size_t)jlo * DD + od;
        float a0 = 0.f, a1 = 0.f, a2 = 0.f, a3 = 0.f;
        int j = 0;
        for (; j + 4 <= nj; j += 4) {
            a0 += sc[hh][j+0] * vb[(size_t)(j+0)*DD];
            a1 += sc[hh][j+1] * vb[(size_t)(j+1)*DD];
            a2 += sc[hh][j+2] * vb[(size_t)(j+2)*DD];
            a3 += sc[hh][j+3] * vb[(size_t)(j+3)*DD];
        }
        for (; j < nj; j++) a0 += sc[hh][j] * vb[(size_t)j*DD];
        g_attnh[(size_t)token * DD + od] = __float2half_rn((a0 + a1 + a2 + a3) * invs[hh]);
    }
}

// ---------------- launch ----------------
extern "C" void kernel_launch(void* const* d_in, const int* in_sizes, int n_in,
                              void* d_out, int out_size) {
    const float* x      = (const float*)d_in[0];
    const float* gate_w = (const float*)d_in[1];
    const float* q_w    = (const float*)d_in[2];
    const float* k_w    = (const float*)d_in[3];
    const float* v_w    = (const float*)d_in[4];
    const float* w1     = (const float*)d_in[5];
    const float* vg     = (const float*)d_in[6];
    const float* w2     = (const float*)d_in[7];
    const float* out_w  = (const float*)d_in[8];
    float* out = (float*)d_out;

    void *pK, *pV, *pQ, *pHb, *pXH, *pAH, *pHh, *pYh, *pS, *pO;
    void *pqT, *pkT, *pvT, *pw1T, *pvgT, *pw2T, *poT;
    cudaGetSymbolAddress(&pK, g_K);
    cudaGetSymbolAddress(&pV, g_V);
    cudaGetSymbolAddress(&pQ, g_Q);
    cudaGetSymbolAddress(&pHb, g_Hb);
    cudaGetSymbolAddress(&pXH, g_xh);
    cudaGetSymbolAddress(&pAH, g_attnh);
    cudaGetSymbolAddress(&pHh, g_Hh);
    cudaGetSymbolAddress(&pYh, g_Yh);
    cudaGetSymbolAddress(&pS, g_sorted);
    cudaGetSymbolAddress(&pO, g_offs);
    cudaGetSymbolAddress(&pqT, g_qT);
    cudaGetSymbolAddress(&pkT, g_kT);
    cudaGetSymbolAddress(&pvT, g_vT);
    cudaGetSymbolAddress(&pw1T, g_w1T);
    cudaGetSymbolAddress(&pvgT, g_vgT);
    cudaGetSymbolAddress(&pw2T, g_w2T);
    cudaGetSymbolAddress(&poT, g_outT);
    const int* sortedp = (const int*)pS;
    const int* offsp   = (const int*)pO;

    const int SM_B = 4 * STG_AB;   // 81920 B
    cudaFuncSetAttribute(gemm_h<false,false>, cudaFuncAttributeMaxDynamicSharedMemorySize, SM_B);
    cudaFuncSetAttribute(gemm_h<true, false>, cudaFuncAttributeMaxDynamicSharedMemorySize, SM_B);
    cudaFuncSetAttribute(gemm_h<true, true >, cudaFuncAttributeMaxDynamicSharedMemorySize, SM_B);

    // weight transposes + fp16 convert -> [N][K]
    transposeh_k<<<dim3(24, 24, NE), dim3(32, 8)>>>(q_w,   (__half*)pqT,  DD, DD);
    transposeh_k<<<dim3(24, 24, NE), dim3(32, 8)>>>(k_w,   (__half*)pkT,  DD, DD);
    transposeh_k<<<dim3(24, 24, NE), dim3(32, 8)>>>(v_w,   (__half*)pvT,  DD, DD);
    transposeh_k<<<dim3(96, 24, NE), dim3(32, 8)>>>(w1,    (__half*)pw1T, DD, FF);
    transposeh_k<<<dim3(96, 24, NE), dim3(32, 8)>>>(vg,    (__half*)pvgT, DD, FF);
    transposeh_k<<<dim3(24, 96, NE), dim3(32, 8)>>>(w2,    (__half*)pw2T, FF, DD);
    transposeh_k<<<dim3(24, 24, 1),  dim3(32, 8)>>>(out_w, (__half*)poT,  DD, DD);

    xconvh_k<<<(NTOK * DD) / 256, 256>>>(x, (__half*)pXH);
    init_k<<<1, 32>>>();
    router_k<<<NTOK / 8, 256>>>(x, gate_w);
    offs_k<<<1, 32>>>(out, (long long)out_size);
    scatter_k<<<NTOK / 256, 256>>>();
    xbar_k<<<NB, 256>>>(x);
    kbar2_k<<<NE, 256>>>(k_w);

    SlotH sK  = { (const __half*)pkT,  pK,  (unsigned long long)DD*DD, (unsigned long long)NTOK*DD, 0 };
    SlotH sV  = { (const __half*)pvT,  pV,  (unsigned long long)DD*DD, (unsigned long long)NTOK*DD, 0 };
    SlotH sQ  = { (const __half*)pqT,  pQ,  (unsigned long long)DD*DD, 0ull, 1 };
    SlotH sW1 = { (const __half*)pw1T, pHb, (unsigned long long)DD*FF, 0ull, 1 };
    SlotH sVG = { (const __half*)pvgT, pHh, (unsigned long long)DD*FF, 0ull, 1 };
    SlotH sW2 = { (const __half*)pw2T, pYh, (unsigned long long)FF*DD, 0ull, 1 };
    SlotH sOW = { (const __half*)poT,  d_out, 0ull, 0ull, 0 };

    // K, V (dense) + Q (gathered) in one launch: slot = blockIdx.x / 6; fp32 outputs
    gemm_h<false,false><<<dim3(18, 16, 8), 256, SM_B>>>(
        (const __half*)pXH, DD, DD, 6, sK, sV, sQ, sortedp, offsp, nullptr);

    attn_k<<<NTOK, 384>>>();

    // SwiGLU: z = attn @ w1 (fp32), then h = silu(z) * (attn @ vg) -> fp16
    gemm_h<false,false><<<dim3(24, 16, 8), 256, SM_B>>>(
        (const __half*)pAH, FF, DD, 24, sW1, sW1, sW1, sortedp, offsp, nullptr);
    gemm_h<true,true><<<dim3(24, 16, 8), 256, SM_B>>>(
        (const __half*)pAH, FF, DD, 24, sVG, sVG, sVG, sortedp, offsp, (const float*)pHb);

    // down projection (gathered, K=3072) -> fp16
    gemm_h<true,false><<<dim3(6, 16, 8), 256, SM_B>>>(
        (const __half*)pHh, DD, FF, 6, sW2, sW2, sW2, sortedp, offsp, nullptr);

    // final output projection (dense) -> fp32 d_out
    gemm_h<false,false><<<dim3(6, 16, 1), 256, SM_B>>>(
        (const __half*)pYh, DD, DD, 6, sOW, sOW, sOW, sortedp, offsp, nullptr);
}

// round 12
// speedup vs baseline: 1.3335x; 1.0572x over previous
#include <cuda_runtime.h>
#include <cuda_fp16.h>
#include <math.h>
#include <stdint.h>

// ---------------- problem constants ----------------
#define DD    768
#define FF    3072
#define NE    8
#define NB    2
#define NL    1024
#define NTOK  2048
#define NH    12
#define HD    64
#define WINW  128
#define NOUT  (NTOK*DD)

// ---------------- device scratch ----------------
__device__ __half g_K[NE*NTOK*DD];        // K in fp16 (halved traffic)
__device__ __half g_V[NE*NTOK*DD];        // V in fp16
__device__ float  g_Q[NTOK*DD];
__device__ float  g_Hb[NTOK*FF];          // z (fp32) for SwiGLU
__device__ __half g_xh[NTOK*DD];          // x in fp16 (RN)
__device__ __half g_attnh[NTOK*DD];       // attention output in fp16
__device__ __half g_Hh[NTOK*FF];          // silu(z)*gate in fp16
__device__ __half g_Yh[NTOK*DD];          // down-proj output in fp16
__device__ float  g_xbar[NB*DD];
__device__ float  g_kbar[NE*NB*DD];
__device__ int    g_idx[NTOK];
__device__ int    g_sorted[NTOK];
__device__ int    g_counts[NE];
__device__ int    g_cursor[NE];
__device__ int    g_offs[NE+1];
__device__ float  g_Psum[NE];
// transposed fp16 weights [N][K] per expert
__device__ __half g_qT[NE*DD*DD];
__device__ __half g_kT[NE*DD*DD];
__device__ __half g_vT[NE*DD*DD];
__device__ __half g_w1T[NE*DD*FF];
__device__ __half g_vgT[NE*DD*FF];
__device__ __half g_w2T[NE*FF*DD];
__device__ __half g_outT[DD*DD];

// ---------------- PTX helpers ----------------
__device__ __forceinline__ uint32_t smem_u32(const void* p) {
    uint32_t a;
    asm("{ .reg .u64 t; cvta.to.shared.u64 t, %1; cvt.u32.u64 %0, t; }" : "=r"(a) : "l"(p));
    return a;
}
__device__ __forceinline__ void cp16(uint32_t s, const void* g) {
    asm volatile("cp.async.cg.shared.global [%0], [%1], 16;" :: "r"(s), "l"(g) : "memory");
}
__device__ __forceinline__ void cp_commit() {
    asm volatile("cp.async.commit_group;" ::: "memory");
}
template<int N> __device__ __forceinline__ void cp_wait() {
    asm volatile("cp.async.wait_group %0;" :: "n"(N) : "memory");
}
__device__ __forceinline__ void mma16(float* c, const uint32_t* a, const uint32_t* b) {
    asm volatile("mma.sync.aligned.m16n8k16.row.col.f32.f16.f16.f32 "
        "{%0,%1,%2,%3}, {%4,%5,%6,%7}, {%8,%9}, {%0,%1,%2,%3};"
        : "+f"(c[0]), "+f"(c[1]), "+f"(c[2]), "+f"(c[3])
        : "r"(a[0]), "r"(a[1]), "r"(a[2]), "r"(a[3]), "r"(b[0]), "r"(b[1]));
}
__device__ __forceinline__ void ldsm4(uint32_t* r, uint32_t addr) {
    asm volatile("ldmatrix.sync.aligned.m8n8.x4.shared.b16 {%0,%1,%2,%3}, [%4];"
        : "=r"(r[0]), "=r"(r[1]), "=r"(r[2]), "=r"(r[3]) : "r"(addr));
}

// ---------------- init / router / offs / scatter ----------------
__global__ void init_k() {
    int t = threadIdx.x;
    if (t < NE) { g_counts[t] = 0; g_Psum[t] = 0.f; }
}

__global__ __launch_bounds__(256) void router_k(const float* __restrict__ x,
                                                const float* __restrict__ gw) {
    int gtid = blockIdx.x * 256 + threadIdx.x;
    int tok  = gtid >> 5;
    int lane = gtid & 31;
    if (tok >= NTOK) return;
    const float* xr = x + (size_t)tok * DD;
    float acc[NE];
#pragma unroll
    for (int e = 0; e < NE; e++) acc[e] = 0.f;
    for (int d = lane; d < DD; d += 32) {
        float xv = xr[d];
        const float* g = gw + (size_t)d * NE;
#pragma unroll
        for (int e = 0; e < NE; e++) acc[e] += xv * g[e];
    }
#pragma unroll
    for (int e = 0; e < NE; e++)
#pragma unroll
        for (int off = 16; off; off >>= 1)
            acc[e] += __shfl_xor_sync(0xffffffffu, acc[e], off);
    if (lane == 0) {
        float l[NE]; float mx = -1e30f;
#pragma unroll
        for (int e = 0; e < NE; e++) { l[e] = acc[e] * 0.5f; mx = fmaxf(mx, l[e]); }
        int best = 0; float bv = l[0];
#pragma unroll
        for (int e = 1; e < NE; e++) if (l[e] > bv) { bv = l[e]; best = e; }
        g_idx[tok] = best;
        atomicAdd(&g_counts[best], 1);
        float p[NE]; float se = 0.f;
#pragma unroll
        for (int e = 0; e < NE; e++) { p[e] = expf(l[e] - mx); se += p[e]; }
        float inv = 1.f / se;
#pragma unroll
        for (int e = 0; e < NE; e++) atomicAdd(&g_Psum[e], p[e] * inv);
    }
}

__global__ void offs_k(float* __restrict__ dout, long long out_size) {
    if (threadIdx.x == 0 && blockIdx.x == 0) {
        int o = 0;
        for (int e = 0; e < NE; e++) { g_offs[e] = o; g_cursor[e] = o; o += g_counts[e]; }
        g_offs[NE] = o;
        float aux = 0.f;
        for (int e = 0; e < NE; e++) aux += (float)g_counts[e] * g_Psum[e];
        aux *= (float)NE / ((float)NTOK * (float)NTOK);
        if (out_size > (long long)NOUT) dout[NOUT] = aux;
    }
}

__global__ void scatter_k() {
    int t = blockIdx.x * 256 + threadIdx.x;
    if (t < NTOK) {
        int e = g_idx[t];
        int p = atomicAdd(&g_cursor[e], 1);
        g_sorted[p] = t;
    }
}

// ---------------- x -> fp16 copy ----------------
__global__ __launch_bounds__(256) void xconvh_k(const float* __restrict__ x, __half* __restrict__ xh) {
    int i = blockIdx.x * 256 + threadIdx.x;
    if (i < NTOK * DD) xh[i] = __float2half_rn(x[i]);
}

// ---------------- x column means per batch ----------------
__global__ __launch_bounds__(256) void xbar_k(const float* __restrict__ x) {
    int b = blockIdx.x;
    for (int d = threadIdx.x; d < DD; d += 256) {
        float s = 0.f;
        const float* xb = x + (size_t)b * NL * DD + d;
        for (int j = 0; j < NL; j++) s += xb[(size_t)j * DD];
        g_xbar[b * DD + d] = s * (1.f / (float)NL);
    }
}

// ---------------- kbar[e,b,:] = xbar[b,:] @ k_w[e] ----------------
__global__ __launch_bounds__(256) void kbar2_k(const float* __restrict__ k_w) {
    int e = blockIdx.x;
    __shared__ float xs[NB * DD];
    for (int i = threadIdx.x; i < NB * DD; i += 256) xs[i] = g_xbar[i];
    __syncthreads();
    const float* W = k_w + (size_t)e * DD * DD;
    for (int d = threadIdx.x; d < DD; d += 256) {
        float a0 = 0.f, a1 = 0.f;
        for (int dk = 0; dk < DD; dk++) {
            float w = W[(size_t)dk * DD + d];
            a0 += xs[dk] * w;
            a1 += xs[DD + dk] * w;
        }
        g_kbar[(e * NB + 0) * DD + d] = a0;
        g_kbar[(e * NB + 1) * DD + d] = a1;
    }
}

// ---------------- weight transpose + fp16 convert: src[e][K][N] -> dst[e][N][K] half ----------------
__global__ __launch_bounds__(256) void transposeh_k(const float* __restrict__ src,
                                                    __half* __restrict__ dst, int K, int N) {
    __shared__ float t[32][33];
    const float* s = src + (size_t)blockIdx.z * K * N;
    __half* d = dst + (size_t)blockIdx.z * K * N;
    int n0 = blockIdx.x * 32, k0 = blockIdx.y * 32;
    int tx = threadIdx.x, ty = threadIdx.y;
#pragma unroll
    for (int i = 0; i < 32; i += 8)
        t[ty + i][tx] = s[(size_t)(k0 + ty + i) * N + n0 + tx];
    __syncthreads();
#pragma unroll
    for (int i = 0; i < 32; i += 8)
        d[(size_t)(n0 + ty + i) * K + k0 + tx] = __float2half_rn(t[tx][ty + i]);
}

// ---------------- slot descriptor ----------------
struct SlotH {
    const __half* B;            // transposed half weight [N][K]
    void* C;                    // output base (fp32 or fp16 per outh)
    unsigned long long strideB;
    unsigned long long strideC;
    int gather;
    int outh;                   // 1 = write __half, 0 = write float
};

// ---------------- fp16 mma.sync GEMM (m16n8k16) ----------------
// D[m][n] = sum_k A[m][k] * BT[n][k], fp32 accumulate.
// Block tile 128x128x32, 8 warps (2m x 4n), warp tile 64x32, 4-stage cp.async.
// A/B smem tiles: 128 rows x 80B (64B data + 16B pad) -> ldmatrix conflict-free.
// SWIGLU_EPI: out = silu(z)*acc, z from fp32 zbuf. outh runtime per slot.
#define STG_A  10240
#define STG_AB 20480
template<bool SWIGLU_EPI>
__global__ __launch_bounds__(256, 2) void gemm_h(
    const __half* __restrict__ A, int ldc, int K, int nbx,
    SlotH s0, SlotH s1, SlotH s2,
    const int* __restrict__ sorted, const int* __restrict__ offs,
    const float* __restrict__ zbuf)
{
    extern __shared__ char smc[];
    __shared__ int rs[128];
    int which = blockIdx.x / nbx;
    int n0 = (blockIdx.x - which * nbx) * 128;
    const __half* Bb; void* Cb; unsigned long long sB, sC; int gat, outh;
    if (which == 0)      { Bb = s0.B; Cb = s0.C; sB = s0.strideB; sC = s0.strideC; gat = s0.gather; outh = s0.outh; }
    else if (which == 1) { Bb = s1.B; Cb = s1.C; sB = s1.strideB; sC = s1.strideC; gat = s1.gather; outh = s1.outh; }
    else                 { Bb = s2.B; Cb = s2.C; sB = s2.strideB; sC = s2.strideC; gat = s2.gather; outh = s2.outh; }
    int e = blockIdx.z;
    int cnt; const int* rmap;
    if (gat) { int st0 = offs[e]; cnt = offs[e + 1] - st0; rmap = sorted + st0; }
    else     { cnt = NTOK; rmap = nullptr; }
    int m0 = blockIdx.y * 128;
    if (m0 >= cnt) return;
    const __half* Be = Bb + sB * (size_t)e;

    int tid = threadIdx.x;
    if (tid < 128) {
        int ra = m0 + tid;
        int row = (ra < cnt) ? ra : (cnt - 1);
        rs[tid] = rmap ? rmap[row] : row;
    }
    __syncthreads();

    uint32_t sbase = smem_u32(smc);

    const __half* aptr[2]; const __half* bptr[2];
    uint32_t soA[2], soB[2];
#pragma unroll
    for (int i = 0; i < 2; i++) {
        int f = i * 256 + tid;
        int row = f >> 2, c = f & 3;
        aptr[i] = A + (size_t)rs[row] * K + c * 8;
        bptr[i] = Be + (size_t)(n0 + row) * K + c * 8;
        uint32_t so = (uint32_t)(row * 80 + c * 16);
        soA[i] = sbase + so;
        soB[i] = sbase + (uint32_t)STG_A + so;
    }

    int lane = tid & 31, wid = tid >> 5;
    int g = lane >> 2, t4 = lane & 3;
    int wm = wid & 1, wn = wid >> 1;
    int mb0 = wm * 64, nb0 = wn * 32;
    int lr = lane & 7, lg = lane >> 3;

    float c1[4][4][4];
#pragma unroll
    for (int mf = 0; mf < 4; mf++)
#pragma unroll
        for (int nf = 0; nf < 4; nf++)
#pragma unroll
            for (int q = 0; q < 4; q++) c1[mf][nf][q] = 0.f;

    int NIT = K >> 5;

    auto load_tile = [&](int it, int st) {
        uint32_t sb = (uint32_t)st * STG_AB;
        int k0 = it << 5;
#pragma unroll
        for (int i = 0; i < 2; i++) cp16(soA[i] + sb, aptr[i] + k0);
#pragma unroll
        for (int i = 0; i < 2; i++) cp16(soB[i] + sb, bptr[i] + k0);
        cp_commit();
    };

    load_tile(0, 0);
    load_tile(1, 1);
    load_tile(2, 2);

    uint32_t aRowOff = (uint32_t)((lr + (lg & 1) * 8) * 80 + (lg >> 1) * 16);
    uint32_t bRowOff = (uint32_t)((lr + (lg >> 1) * 8) * 80 + (lg & 1) * 16);

    for (int it = 0; it < NIT; it++) {
        int rem = NIT - 1 - it;
        if (rem >= 2) cp_wait<2>(); else if (rem == 1) cp_wait<1>(); else cp_wait<0>();
        __syncthreads();
        int st = it & 3;
        uint32_t Ast = sbase + (uint32_t)st * STG_AB;
        uint32_t Bst = Ast + (uint32_t)STG_A;

#pragma unroll
        for (int kk = 0; kk < 32; kk += 16) {
            uint32_t kbyte = (uint32_t)(kk * 2);
            uint32_t af[4][4];
#pragma unroll
            for (int mf = 0; mf < 4; mf++)
                ldsm4(af[mf], Ast + (uint32_t)((mb0 + mf * 16) * 80) + aRowOff + kbyte);
            uint32_t bf[2][4];
#pragma unroll
            for (int np = 0; np < 2; np++)
                ldsm4(bf[np], Bst + (uint32_t)((nb0 + np * 16) * 80) + bRowOff + kbyte);
#pragma unroll
            for (int mf = 0; mf < 4; mf++)
#pragma unroll
                for (int nf = 0; nf < 4; nf++)
                    mma16(c1[mf][nf], af[mf], &bf[nf >> 1][(nf & 1) * 2]);
        }
        if (it + 3 < NIT) load_tile(it + 3, (it + 3) & 3);
    }

    // ---------------- epilogue ----------------
#pragma unroll
    for (int mf = 0; mf < 4; mf++) {
        int lr0 = mb0 + mf * 16 + g;
        int lr1 = lr0 + 8;
        bool v0 = (m0 + lr0) < cnt;
        bool v1 = (m0 + lr1) < cnt;
        size_t o0 = (size_t)rs[lr0] * ldc + n0 + nb0;
        size_t o1 = (size_t)rs[lr1] * ldc + n0 + nb0;
#pragma unroll
        for (int nf = 0; nf < 4; nf++) {
            int co = nf * 8 + 2 * t4;
            float a0 = c1[mf][nf][0], a1 = c1[mf][nf][1];
            float a2 = c1[mf][nf][2], a3 = c1[mf][nf][3];
            if (SWIGLU_EPI) {
                float2 za = v0 ? *(const float2*)(zbuf + o0 + co) : make_float2(0.f, 0.f);
                float2 zb = v1 ? *(const float2*)(zbuf + o1 + co) : make_float2(0.f, 0.f);
                a0 = za.x / (1.f + expf(-za.x)) * a0;
                a1 = za.y / (1.f + expf(-za.y)) * a1;
                a2 = zb.x / (1.f + expf(-zb.x)) * a2;
                a3 = zb.y / (1.f + expf(-zb.y)) * a3;
            }
            if (outh) {
                __half* C = (__half*)Cb + sC * (size_t)e;
                if (v0) *(__half2*)(C + o0 + co) = __floats2half2_rn(a0, a1);
                if (v1) *(__half2*)(C + o1 + co) = __floats2half2_rn(a2, a3);
            } else {
                float* C = (float*)Cb + sC * (size_t)e;
                if (v0) *(float2*)(C + o0 + co) = make_float2(a0, a1);
                if (v1) *(float2*)(C + o1 + co) = make_float2(a2, a3);
            }
        }
    }
}

// ---------------- sliding-window attention with Reynolds modulation ----------------
// K staged as fp16: 776-half rows (1552 B, 16B-aligned).
#define KHPAD 776
__global__ __launch_bounds__(384) void attn_k() {
    int token = blockIdx.x;
    int b = token >> 10;
    int t = token & (NL - 1);
    int e = g_idx[token];

    __shared__ float qs[DD];
    __shared__ float sc[NH][WINW + 4];
    __shared__ float mh[NH], invs[NH];
    __shared__ __half ks[16][KHPAD];

    int tid = threadIdx.x, lane = tid & 31, h = tid >> 5;
    for (int d = tid; d < DD; d += 384) qs[d] = g_Q[(size_t)token * DD + d];
    __syncthreads();

    int jlo = (t >= WINW - 1) ? t - (WINW - 1) : 0;
    int nj  = t - jlo + 1;
    size_t ebbase = (size_t)(e * NB + b) * NL * DD;
    const __half* Kb = g_K + ebbase;

    // full-row mean via mean key (fp32 path, linearity of dot)
    {
        const float* kb = g_kbar + (size_t)(e * NB + b) * DD + h*64 + lane*2;
        float q0 = qs[h*64 + lane*2], q1 = qs[h*64 + lane*2 + 1];
        float p = q0 * kb[0] + q1 * kb[1];
#pragma unroll
        for (int off = 16; off; off >>= 1) p += __shfl_xor_sync(0xffffffffu, p, off);
        if (lane == 0) mh[h] = p * 0.125f;
    }

    // raw scores; K staged through smem in 16-row half tiles
    int j2 = lane >> 1, half = lane & 1;
    const float* qr = &qs[h*64 + half*32];
    int ntile = (nj + 15) >> 4;
    for (int tt = 0; tt < ntile; tt++) {
        int j0 = tt << 4;
        int rows = nj - j0; if (rows > 16) rows = 16;
        for (int v = tid; v < rows * 96; v += 384) {
            int r = v / 96, c8 = v % 96;
            *(float4*)&ks[r][c8 * 8] = *(const float4*)(Kb + (size_t)(jlo + j0 + r) * DD + c8 * 8);
        }
        __syncthreads();
        const __half2* k2 = (const __half2*)&ks[j2][h*64 + half*32];
        float s = 0.f;
#pragma unroll
        for (int i = 0; i < 16; i++) {
            float2 kf = __half22float2(k2[i]);
            s += qr[2*i] * kf.x + qr[2*i+1] * kf.y;
        }
        s += __shfl_xor_sync(0xffffffffu, s, 1);
        if (half == 0 && j2 < rows) sc[h][j0 + j2] = s * 0.125f;
        __syncthreads();
    }

    // Reynolds modulation + softmax
    float m = mh[h];
    float mx = -1e30f;
    for (int jj = lane; jj < nj; jj += 32) {
        float sv = sc[h][jj];
        float sig = 1.f / (1.f + __expf(-sv));
        float sp = sv + 0.1f * sv - 0.1f * sig * sig - 0.1f * fabsf(sv - m);
        sc[h][jj] = sp;
        mx = fmaxf(mx, sp);
    }
#pragma unroll
    for (int off = 16; off; off >>= 1) mx = fmaxf(mx, __shfl_xor_sync(0xffffffffu, mx, off));
    float sum = 0.f;
    for (int jj = lane; jj < nj; jj += 32) {
        float pexp = __expf(sc[h][jj] - mx);
        sc[h][jj] = pexp;
        sum += pexp;
    }
#pragma unroll
    for (int off = 16; off; off >>= 1) sum += __shfl_xor_sync(0xffffffffu, sum, off);
    if (lane == 0) invs[h] = 1.f / sum;
    __syncthreads();

    // out = attn @ V (half reads, coalesced over d) -> fp16
    const __half* Vb = g_V + ebbase;
    for (int od = tid; od < DD; od += 384) {
        int hh = od >> 6;
        const __half* vb = Vb + (size_t)jlo * DD + od;
        float a0 = 0.f, a1 = 0.f, a2 = 0.f, a3 = 0.f;
        int j = 0;
        for (; j + 4 <= nj; j += 4) {
            a0 += sc[hh][j+0] * __half2float(vb[(size_t)(j+0)*DD]);
            a1 += sc[hh][j+1] * __half2float(vb[(size_t)(j+1)*DD]);
            a2 += sc[hh][j+2] * __half2float(vb[(size_t)(j+2)*DD]);
            a3 += sc[hh][j+3] * __half2float(vb[(size_t)(j+3)*DD]);
        }
        for (; j < nj; j++) a0 += sc[hh][j] * __half2float(vb[(size_t)j*DD]);
        g_attnh[(size_t)token * DD + od] = __float2half_rn((a0 + a1 + a2 + a3) * invs[hh]);
    }
}

// ---------------- launch ----------------
extern "C" void kernel_launch(void* const* d_in, const int* in_sizes, int n_in,
                              void* d_out, int out_size) {
    const float* x      = (const float*)d_in[0];
    const float* gate_w = (const float*)d_in[1];
    const float* q_w    = (const float*)d_in[2];
    const float* k_w    = (const float*)d_in[3];
    const float* v_w    = (const float*)d_in[4];
    const float* w1     = (const float*)d_in[5];
    const float* vg     = (const float*)d_in[6];
    const float* w2     = (const float*)d_in[7];
    const float* out_w  = (const float*)d_in[8];
    float* out = (float*)d_out;

    void *pK, *pV, *pQ, *pHb, *pXH, *pAH, *pHh, *pYh, *pS, *pO;
    void *pqT, *pkT, *pvT, *pw1T, *pvgT, *pw2T, *poT;
    cudaGetSymbolAddress(&pK, g_K);
    cudaGetSymbolAddress(&pV, g_V);
    cudaGetSymbolAddress(&pQ, g_Q);
    cudaGetSymbolAddress(&pHb, g_Hb);
    cudaGetSymbolAddress(&pXH, g_xh);
    cudaGetSymbolAddress(&pAH, g_attnh);
    cudaGetSymbolAddress(&pHh, g_Hh);
    cudaGetSymbolAddress(&pYh, g_Yh);
    cudaGetSymbolAddress(&pS, g_sorted);
    cudaGetSymbolAddress(&pO, g_offs);
    cudaGetSymbolAddress(&pqT, g_qT);
    cudaGetSymbolAddress(&pkT, g_kT);
    cudaGetSymbolAddress(&pvT, g_vT);
    cudaGetSymbolAddress(&pw1T, g_w1T);
    cudaGetSymbolAddress(&pvgT, g_vgT);
    cudaGetSymbolAddress(&pw2T, g_w2T);
    cudaGetSymbolAddress(&poT, g_outT);
    const int* sortedp = (const int*)pS;
    const int* offsp   = (const int*)pO;

    const int SM_B = 4 * STG_AB;   // 81920 B
    cudaFuncSetAttribute(gemm_h<false>, cudaFuncAttributeMaxDynamicSharedMemorySize, SM_B);
    cudaFuncSetAttribute(gemm_h<true >, cudaFuncAttributeMaxDynamicSharedMemorySize, SM_B);

    // weight transposes + fp16 convert -> [N][K]
    transposeh_k<<<dim3(24, 24, NE), dim3(32, 8)>>>(q_w,   (__half*)pqT,  DD, DD);
    transposeh_k<<<dim3(24, 24, NE), dim3(32, 8)>>>(k_w,   (__half*)pkT,  DD, DD);
    transposeh_k<<<dim3(24, 24, NE), dim3(32, 8)>>>(v_w,   (__half*)pvT,  DD, DD);
    transposeh_k<<<dim3(96, 24, NE), dim3(32, 8)>>>(w1,    (__half*)pw1T, DD, FF);
    transposeh_k<<<dim3(96, 24, NE), dim3(32, 8)>>>(vg,    (__half*)pvgT, DD, FF);
    transposeh_k<<<dim3(24, 96, NE), dim3(32, 8)>>>(w2,    (__half*)pw2T, FF, DD);
    transposeh_k<<<dim3(24, 24, 1),  dim3(32, 8)>>>(out_w, (__half*)poT,  DD, DD);

    xconvh_k<<<(NTOK * DD) / 256, 256>>>(x, (__half*)pXH);
    init_k<<<1, 32>>>();
    router_k<<<NTOK / 8, 256>>>(x, gate_w);
    offs_k<<<1, 32>>>(out, (long long)out_size);
    scatter_k<<<NTOK / 256, 256>>>();
    xbar_k<<<NB, 256>>>(x);
    kbar2_k<<<NE, 256>>>(k_w);

    SlotH sK  = { (const __half*)pkT,  pK,  (unsigned long long)DD*DD, (unsigned long long)NTOK*DD, 0, 1 };
    SlotH sV  = { (const __half*)pvT,  pV,  (unsigned long long)DD*DD, (unsigned long long)NTOK*DD, 0, 1 };
    SlotH sQ  = { (const __half*)pqT,  pQ,  (unsigned long long)DD*DD, 0ull, 1, 0 };
    SlotH sW1 = { (const __half*)pw1T, pHb, (unsigned long long)DD*FF, 0ull, 1, 0 };
    SlotH sVG = { (const __half*)pvgT, pHh, (unsigned long long)DD*FF, 0ull, 1, 1 };
    SlotH sW2 = { (const __half*)pw2T, pYh, (unsigned long long)FF*DD, 0ull, 1, 1 };
    SlotH sOW = { (const __half*)poT,  d_out, 0ull, 0ull, 0, 0 };

    // K, V (dense, fp16 out) + Q (gathered, fp32 out) in one launch
    gemm_h<false><<<dim3(18, 16, 8), 256, SM_B>>>(
        (const __half*)pXH, DD, DD, 6, sK, sV, sQ, sortedp, offsp, nullptr);

    attn_k<<<NTOK, 384>>>();

    // SwiGLU: z = attn @ w1 (fp32), then h = silu(z) * (attn @ vg) -> fp16
    gemm_h<false><<<dim3(24, 16, 8), 256, SM_B>>>(
        (const __half*)pAH, FF, DD, 24, sW1, sW1, sW1, sortedp, offsp, nullptr);
    gemm_h<true><<<dim3(24, 16, 8), 256, SM_B>>>(
        (const __half*)pAH, FF, DD, 24, sVG, sVG, sVG, sortedp, offsp, (const float*)pHb);

    // down projection (gathered, K=3072) -> fp16
    gemm_h<false><<<dim3(6, 16, 8), 256, SM_B>>>(
        (const __half*)pHh, DD, FF, 6, sW2, sW2, sW2, sortedp, offsp, nullptr);

    // final output projection (dense) -> fp32 d_out
    gemm_h<false><<<dim3(6, 16, 1), 256, SM_B>>>(
        (const __half*)pYh, DD, DD, 6, sOW, sOW, sOW, sortedp, offsp, nullptr);
}

// round 13
// speedup vs baseline: 1.3974x; 1.0480x over previous
#include <cuda_runtime.h>
#include <cuda_fp16.h>
#include <math.h>
#include <stdint.h>

// ---------------- problem constants ----------------
#define DD    768
#define FF    3072
#define NE    8
#define NB    2
#define NL    1024
#define NTOK  2048
#define NH    12
#define HD    64
#define WINW  128
#define NOUT  (NTOK*DD)

// ---------------- device scratch ----------------
__device__ __half g_K[NE*NTOK*DD];
__device__ __half g_V[NE*NTOK*DD];
__device__ float  g_Q[NTOK*DD];
__device__ __half g_xh[NTOK*DD];
__device__ __half g_attnh[NTOK*DD];
__device__ __half g_Hh[NTOK*FF];
__device__ __half g_Yh[NTOK*DD];
__device__ float  g_xbar[NB*DD];
__device__ float  g_kbar[NE*NB*DD];
__device__ int    g_idx[NTOK];
__device__ int    g_sorted[NTOK];
__device__ int    g_counts[NE];
__device__ int    g_cursor[NE];
__device__ int    g_offs[NE+1];
__device__ float  g_Psum[NE];
// transposed fp16 weights [N][K] per expert
__device__ __half g_qT[NE*DD*DD];
__device__ __half g_kT[NE*DD*DD];
__device__ __half g_vT[NE*DD*DD];
__device__ __half g_w1T[NE*DD*FF];
__device__ __half g_vgT[NE*DD*FF];
__device__ __half g_w2T[NE*FF*DD];
__device__ __half g_outT[DD*DD];

// ---------------- PTX helpers ----------------
__device__ __forceinline__ uint32_t smem_u32(const void* p) {
    uint32_t a;
    asm("{ .reg .u64 t; cvta.to.shared.u64 t, %1; cvt.u32.u64 %0, t; }" : "=r"(a) : "l"(p));
    return a;
}
__device__ __forceinline__ void cp16(uint32_t s, const void* g) {
    asm volatile("cp.async.cg.shared.global [%0], [%1], 16;" :: "r"(s), "l"(g) : "memory");
}
__device__ __forceinline__ void cp_commit() {
    asm volatile("cp.async.commit_group;" ::: "memory");
}
template<int N> __device__ __forceinline__ void cp_wait() {
    asm volatile("cp.async.wait_group %0;" :: "n"(N) : "memory");
}
__device__ __forceinline__ void mma16(float* c, const uint32_t* a, const uint32_t* b) {
    asm volatile("mma.sync.aligned.m16n8k16.row.col.f32.f16.f16.f32 "
        "{%0,%1,%2,%3}, {%4,%5,%6,%7}, {%8,%9}, {%0,%1,%2,%3};"
        : "+f"(c[0]), "+f"(c[1]), "+f"(c[2]), "+f"(c[3])
        : "r"(a[0]), "r"(a[1]), "r"(a[2]), "r"(a[3]), "r"(b[0]), "r"(b[1]));
}
__device__ __forceinline__ void ldsm4(uint32_t* r, uint32_t addr) {
    asm volatile("ldmatrix.sync.aligned.m8n8.x4.shared.b16 {%0,%1,%2,%3}, [%4];"
        : "=r"(r[0]), "=r"(r[1]), "=r"(r[2]), "=r"(r[3]) : "r"(addr));
}

// ---------------- init / router / offs / scatter ----------------
__global__ void init_k() {
    int t = threadIdx.x;
    if (t < NE) { g_counts[t] = 0; g_Psum[t] = 0.f; }
}

__global__ __launch_bounds__(256) void router_k(const float* __restrict__ x,
                                                const float* __restrict__ gw) {
    int gtid = blockIdx.x * 256 + threadIdx.x;
    int tok  = gtid >> 5;
    int lane = gtid & 31;
    if (tok >= NTOK) return;
    const float* xr = x + (size_t)tok * DD;
    float acc[NE];
#pragma unroll
    for (int e = 0; e < NE; e++) acc[e] = 0.f;
    for (int d = lane; d < DD; d += 32) {
        float xv = xr[d];
        const float* g = gw + (size_t)d * NE;
#pragma unroll
        for (int e = 0; e < NE; e++) acc[e] += xv * g[e];
    }
#pragma unroll
    for (int e = 0; e < NE; e++)
#pragma unroll
        for (int off = 16; off; off >>= 1)
            acc[e] += __shfl_xor_sync(0xffffffffu, acc[e], off);
    if (lane == 0) {
        float l[NE]; float mx = -1e30f;
#pragma unroll
        for (int e = 0; e < NE; e++) { l[e] = acc[e] * 0.5f; mx = fmaxf(mx, l[e]); }
        int best = 0; float bv = l[0];
#pragma unroll
        for (int e = 1; e < NE; e++) if (l[e] > bv) { bv = l[e]; best = e; }
        g_idx[tok] = best;
        atomicAdd(&g_counts[best], 1);
        float p[NE]; float se = 0.f;
#pragma unroll
        for (int e = 0; e < NE; e++) { p[e] = expf(l[e] - mx); se += p[e]; }
        float inv = 1.f / se;
#pragma unroll
        for (int e = 0; e < NE; e++) atomicAdd(&g_Psum[e], p[e] * inv);
    }
}

__global__ void offs_k(float* __restrict__ dout, long long out_size) {
    if (threadIdx.x == 0 && blockIdx.x == 0) {
        int o = 0;
        for (int e = 0; e < NE; e++) { g_offs[e] = o; g_cursor[e] = o; o += g_counts[e]; }
        g_offs[NE] = o;
        float aux = 0.f;
        for (int e = 0; e < NE; e++) aux += (float)g_counts[e] * g_Psum[e];
        aux *= (float)NE / ((float)NTOK * (float)NTOK);
        if (out_size > (long long)NOUT) dout[NOUT] = aux;
    }
}

__global__ void scatter_k() {
    int t = blockIdx.x * 256 + threadIdx.x;
    if (t < NTOK) {
        int e = g_idx[t];
        int p = atomicAdd(&g_cursor[e], 1);
        g_sorted[p] = t;
    }
}

// ---------------- x -> fp16 copy ----------------
__global__ __launch_bounds__(256) void xconvh_k(const float* __restrict__ x, __half* __restrict__ xh) {
    int i = blockIdx.x * 256 + threadIdx.x;
    if (i < NTOK * DD) xh[i] = __float2half_rn(x[i]);
}

// ---------------- x column means per batch ----------------
__global__ __launch_bounds__(256) void xbar_k(const float* __restrict__ x) {
    int b = blockIdx.x;
    for (int d = threadIdx.x; d < DD; d += 256) {
        float s = 0.f;
        const float* xb = x + (size_t)b * NL * DD + d;
        for (int j = 0; j < NL; j++) s += xb[(size_t)j * DD];
        g_xbar[b * DD + d] = s * (1.f / (float)NL);
    }
}

// ---------------- kbar[e,b,:] = xbar[b,:] @ k_w[e] ----------------
__global__ __launch_bounds__(256) void kbar2_k(const float* __restrict__ k_w) {
    int e = blockIdx.x;
    __shared__ float xs[NB * DD];
    for (int i = threadIdx.x; i < NB * DD; i += 256) xs[i] = g_xbar[i];
    __syncthreads();
    const float* W = k_w + (size_t)e * DD * DD;
    for (int d = threadIdx.x; d < DD; d += 256) {
        float a0 = 0.f, a1 = 0.f;
        for (int dk = 0; dk < DD; dk++) {
            float w = W[(size_t)dk * DD + d];
            a0 += xs[dk] * w;
            a1 += xs[DD + dk] * w;
        }
        g_kbar[(e * NB + 0) * DD + d] = a0;
        g_kbar[(e * NB + 1) * DD + d] = a1;
    }
}

// ---------------- weight transpose + fp16 convert: src[e][K][N] -> dst[e][N][K] half ----------------
// 64k x 32n tile; writes are half2 -> 128B per warp (coalesced).
__global__ __launch_bounds__(256) void transposeh_k(const float* __restrict__ src,
                                                    __half* __restrict__ dst, int K, int N) {
    __shared__ float t[64][33];
    const float* s = src + (size_t)blockIdx.z * K * N;
    __half* d = dst + (size_t)blockIdx.z * K * N;
    int n0 = blockIdx.x * 32, k0 = blockIdx.y * 64;
    int tx = threadIdx.x, ty = threadIdx.y;
#pragma unroll
    for (int i = 0; i < 64; i += 8)
        t[ty + i][tx] = s[(size_t)(k0 + ty + i) * N + n0 + tx];
    __syncthreads();
#pragma unroll
    for (int i = 0; i < 32; i += 8) {
        int r = ty + i;
        __half2 h = __floats2half2_rn(t[2 * tx][r], t[2 * tx + 1][r]);
        *(__half2*)(d + (size_t)(n0 + r) * K + k0 + 2 * tx) = h;
    }
}

// ---------------- slot descriptor ----------------
struct SlotH {
    const __half* B;
    void* C;
    unsigned long long strideB;
    unsigned long long strideC;
    int gather;
    int outh;                   // 1 = write __half, 0 = write float
};

// ---------------- fp16 mma.sync GEMM (m16n8k16), single-B ----------------
// Block tile 128x128x32, 8 warps (2m x 4n), warp tile 64x32, 4-stage cp.async.
#define STG_A  10240
#define STG_AB 20480
__global__ __launch_bounds__(256, 2) void gemm_h(
    const __half* __restrict__ A, int ldc, int K, int nbx,
    SlotH s0, SlotH s1, SlotH s2,
    const int* __restrict__ sorted, const int* __restrict__ offs)
{
    extern __shared__ char smc[];
    __shared__ int rs[128];
    int which = blockIdx.x / nbx;
    int n0 = (blockIdx.x - which * nbx) * 128;
    const __half* Bb; void* Cb; unsigned long long sB, sC; int gat, outh;
    if (which == 0)      { Bb = s0.B; Cb = s0.C; sB = s0.strideB; sC = s0.strideC; gat = s0.gather; outh = s0.outh; }
    else if (which == 1) { Bb = s1.B; Cb = s1.C; sB = s1.strideB; sC = s1.strideC; gat = s1.gather; outh = s1.outh; }
    else                 { Bb = s2.B; Cb = s2.C; sB = s2.strideB; sC = s2.strideC; gat = s2.gather; outh = s2.outh; }
    int e = blockIdx.z;
    int cnt; const int* rmap;
    if (gat) { int st0 = offs[e]; cnt = offs[e + 1] - st0; rmap = sorted + st0; }
    else     { cnt = NTOK; rmap = nullptr; }
    int m0 = blockIdx.y * 128;
    if (m0 >= cnt) return;
    const __half* Be = Bb + sB * (size_t)e;

    int tid = threadIdx.x;
    if (tid < 128) {
        int ra = m0 + tid;
        int row = (ra < cnt) ? ra : (cnt - 1);
        rs[tid] = rmap ? rmap[row] : row;
    }
    __syncthreads();

    uint32_t sbase = smem_u32(smc);

    const __half* aptr[2]; const __half* bptr[2];
    uint32_t soA[2], soB[2];
#pragma unroll
    for (int i = 0; i < 2; i++) {
        int f = i * 256 + tid;
        int row = f >> 2, c = f & 3;
        aptr[i] = A + (size_t)rs[row] * K + c * 8;
        bptr[i] = Be + (size_t)(n0 + row) * K + c * 8;
        uint32_t so = (uint32_t)(row * 80 + c * 16);
        soA[i] = sbase + so;
        soB[i] = sbase + (uint32_t)STG_A + so;
    }

    int lane = tid & 31, wid = tid >> 5;
    int g = lane >> 2, t4 = lane & 3;
    int wm = wid & 1, wn = wid >> 1;
    int mb0 = wm * 64, nb0 = wn * 32;
    int lr = lane & 7, lg = lane >> 3;

    float c1[4][4][4];
#pragma unroll
    for (int mf = 0; mf < 4; mf++)
#pragma unroll
        for (int nf = 0; nf < 4; nf++)
#pragma unroll
            for (int q = 0; q < 4; q++) c1[mf][nf][q] = 0.f;

    int NIT = K >> 5;

    auto load_tile = [&](int it, int st) {
        uint32_t sb = (uint32_t)st * STG_AB;
        int k0 = it << 5;
#pragma unroll
        for (int i = 0; i < 2; i++) cp16(soA[i] + sb, aptr[i] + k0);
#pragma unroll
        for (int i = 0; i < 2; i++) cp16(soB[i] + sb, bptr[i] + k0);
        cp_commit();
    };

    load_tile(0, 0);
    load_tile(1, 1);
    load_tile(2, 2);

    uint32_t aRowOff = (uint32_t)((lr + (lg & 1) * 8) * 80 + (lg >> 1) * 16);
    uint32_t bRowOff = (uint32_t)((lr + (lg >> 1) * 8) * 80 + (lg & 1) * 16);

    for (int it = 0; it < NIT; it++) {
        int rem = NIT - 1 - it;
        if (rem >= 2) cp_wait<2>(); else if (rem == 1) cp_wait<1>(); else cp_wait<0>();
        __syncthreads();
        int st = it & 3;
        uint32_t Ast = sbase + (uint32_t)st * STG_AB;
        uint32_t Bst = Ast + (uint32_t)STG_A;

#pragma unroll
        for (int kk = 0; kk < 32; kk += 16) {
            uint32_t kbyte = (uint32_t)(kk * 2);
            uint32_t af[4][4];
#pragma unroll
            for (int mf = 0; mf < 4; mf++)
                ldsm4(af[mf], Ast + (uint32_t)((mb0 + mf * 16) * 80) + aRowOff + kbyte);
            uint32_t bf[2][4];
#pragma unroll
            for (int np = 0; np < 2; np++)
                ldsm4(bf[np], Bst + (uint32_t)((nb0 + np * 16) * 80) + bRowOff + kbyte);
#pragma unroll
            for (int mf = 0; mf < 4; mf++)
#pragma unroll
                for (int nf = 0; nf < 4; nf++)
                    mma16(c1[mf][nf], af[mf], &bf[nf >> 1][(nf & 1) * 2]);
        }
        if (it + 3 < NIT) load_tile(it + 3, (it + 3) & 3);
    }

    // ---------------- epilogue ----------------
#pragma unroll
    for (int mf = 0; mf < 4; mf++) {
        int lr0 = mb0 + mf * 16 + g;
        int lr1 = lr0 + 8;
        bool v0 = (m0 + lr0) < cnt;
        bool v1 = (m0 + lr1) < cnt;
        size_t o0 = (size_t)rs[lr0] * ldc + n0 + nb0;
        size_t o1 = (size_t)rs[lr1] * ldc + n0 + nb0;
#pragma unroll
        for (int nf = 0; nf < 4; nf++) {
            int co = nf * 8 + 2 * t4;
            float a0 = c1[mf][nf][0], a1 = c1[mf][nf][1];
            float a2 = c1[mf][nf][2], a3 = c1[mf][nf][3];
            if (outh) {
                __half* C = (__half*)Cb + sC * (size_t)e;
                if (v0) *(__half2*)(C + o0 + co) = __floats2half2_rn(a0, a1);
                if (v1) *(__half2*)(C + o1 + co) = __floats2half2_rn(a2, a3);
            } else {
                float* C = (float*)Cb + sC * (size_t)e;
                if (v0) *(float2*)(C + o0 + co) = make_float2(a0, a1);
                if (v1) *(float2*)(C + o1 + co) = make_float2(a2, a3);
            }
        }
    }
}

// ---------------- fused SwiGLU dual GEMM: h = silu(A@w1) * (A@vg) ----------------
// Block tile 128x64x32, dual B, 8 warps (2m x 4n), warp tile 64x16 per output.
// Stage = A(10240) + B1(5120) + B2(5120) = 20480 (same as gemm_h); 4 stages.
#define STG_B2 5120
__global__ __launch_bounds__(256, 2) void gemm_swiglu(
    const __half* __restrict__ A,
    const __half* __restrict__ W1, const __half* __restrict__ VG,
    __half* __restrict__ C,
    const int* __restrict__ sorted, const int* __restrict__ offs)
{
    extern __shared__ char smc[];
    __shared__ int rs[128];
    const int K = DD, ldc = FF;
    int n0 = blockIdx.x * 64;
    int e = blockIdx.z;
    int st0 = offs[e];
    int cnt = offs[e + 1] - st0;
    const int* rmap = g_sorted + st0;
    int m0 = blockIdx.y * 128;
    if (m0 >= cnt) return;
    const __half* B1e = W1 + (size_t)e * DD * FF;
    const __half* B2e = VG + (size_t)e * DD * FF;

    int tid = threadIdx.x;
    if (tid < 128) {
        int ra = m0 + tid;
        int row = (ra < cnt) ? ra : (cnt - 1);
        rs[tid] = rmap ? rmap[row] : row;
    }
    __syncthreads();

    uint32_t sbase = smem_u32(smc);

    const __half* aptr[2]; const __half* b1p; const __half* b2p;
    uint32_t soA[2], soB;
#pragma unroll
    for (int i = 0; i < 2; i++) {
        int f = i * 256 + tid;
        int row = f >> 2, c = f & 3;
        aptr[i] = A + (size_t)rs[row] * K + c * 8;
        soA[i]  = sbase + (uint32_t)(row * 80 + c * 16);
    }
    {
        int row = tid >> 2, c = tid & 3;      // 64 rows x 4 chunks = 256
        b1p = B1e + (size_t)(n0 + row) * K + c * 8;
        b2p = B2e + (size_t)(n0 + row) * K + c * 8;
        soB = sbase + (uint32_t)STG_A + (uint32_t)(row * 80 + c * 16);
    }

    int lane = tid & 31, wid = tid >> 5;
    int g = lane >> 2, t4 = lane & 3;
    int wm = wid & 1, wn = wid >> 1;
    int mb0 = wm * 64, nb0 = wn * 16;
    int lr = lane & 7, lg = lane >> 3;

    float c1[4][2][4], c2[4][2][4];
#pragma unroll
    for (int mf = 0; mf < 4; mf++)
#pragma unroll
        for (int nf = 0; nf < 2; nf++)
#pragma unroll
            for (int q = 0; q < 4; q++) { c1[mf][nf][q] = 0.f; c2[mf][nf][q] = 0.f; }

    int NIT = K >> 5;   // 24

    auto load_tile = [&](int it, int st) {
        uint32_t sb = (uint32_t)st * STG_AB;
        int k0 = it << 5;
#pragma unroll
        for (int i = 0; i < 2; i++) cp16(soA[i] + sb, aptr[i] + k0);
        cp16(soB + sb, b1p + k0);
        cp16(soB + sb + (uint32_t)STG_B2, b2p + k0);
        cp_commit();
    };

    load_tile(0, 0);
    load_tile(1, 1);
    load_tile(2, 2);

    uint32_t aRowOff = (uint32_t)((lr + (lg & 1) * 8) * 80 + (lg >> 1) * 16);
    uint32_t bRowOff = (uint32_t)((lr + (lg >> 1) * 8) * 80 + (lg & 1) * 16);

    for (int it = 0; it < NIT; it++) {
        int rem = NIT - 1 - it;
        if (rem >= 2) cp_wait<2>(); else if (rem == 1) cp_wait<1>(); else cp_wait<0>();
        __syncthreads();
        int st = it & 3;
        uint32_t Ast = sbase + (uint32_t)st * STG_AB;
        uint32_t B1st = Ast + (uint32_t)STG_A;
        uint32_t B2st = B1st + (uint32_t)STG_B2;

#pragma unroll
        for (int kk = 0; kk < 32; kk += 16) {
            uint32_t kbyte = (uint32_t)(kk * 2);
            uint32_t af[4][4];
#pragma unroll
            for (int mf = 0; mf < 4; mf++)
                ldsm4(af[mf], Ast + (uint32_t)((mb0 + mf * 16) * 80) + aRowOff + kbyte);
            uint32_t b1f[4], b2f[4];
            ldsm4(b1f, B1st + (uint32_t)(nb0 * 80) + bRowOff + kbyte);
            ldsm4(b2f, B2st + (uint32_t)(nb0 * 80) + bRowOff + kbyte);
#pragma unroll
            for (int mf = 0; mf < 4; mf++)
#pragma unroll
                for (int nf = 0; nf < 2; nf++) {
                    mma16(c1[mf][nf], af[mf], &b1f[nf * 2]);
                    mma16(c2[mf][nf], af[mf], &b2f[nf * 2]);
                }
        }
        if (it + 3 < NIT) load_tile(it + 3, (it + 3) & 3);
    }

    // epilogue: h = silu(z) * gate -> fp16
#pragma unroll
    for (int mf = 0; mf < 4; mf++) {
        int lr0 = mb0 + mf * 16 + g;
        int lr1 = lr0 + 8;
        bool v0 = (m0 + lr0) < cnt;
        bool v1 = (m0 + lr1) < cnt;
        __half* p0 = C + (size_t)rs[lr0] * ldc + n0 + nb0;
        __half* p1 = C + (size_t)rs[lr1] * ldc + n0 + nb0;
#pragma unroll
        for (int nf = 0; nf < 2; nf++) {
            int co = nf * 8 + 2 * t4;
            float z0 = c1[mf][nf][0], z1 = c1[mf][nf][1];
            float z2 = c1[mf][nf][2], z3 = c1[mf][nf][3];
            float h0 = z0 / (1.f + expf(-z0)) * c2[mf][nf][0];
            float h1 = z1 / (1.f + expf(-z1)) * c2[mf][nf][1];
            float h2 = z2 / (1.f + expf(-z2)) * c2[mf][nf][2];
            float h3 = z3 / (1.f + expf(-z3)) * c2[mf][nf][3];
            if (v0) *(__half2*)(p0 + co) = __floats2half2_rn(h0, h1);
            if (v1) *(__half2*)(p1 + co) = __floats2half2_rn(h2, h3);
        }
    }
}

// ---------------- sliding-window attention with Reynolds modulation ----------------
#define KHPAD 776
__global__ __launch_bounds__(384) void attn_k() {
    int token = blockIdx.x;
    int b = token >> 10;
    int t = token & (NL - 1);
    int e = g_idx[token];

    __shared__ float qs[DD];
    __shared__ float sc[NH][WINW + 4];
    __shared__ float mh[NH], invs[NH];
    __shared__ __half ks[16][KHPAD];

    int tid = threadIdx.x, lane = tid & 31, h = tid >> 5;
    for (int d = tid; d < DD; d += 384) qs[d] = g_Q[(size_t)token * DD + d];
    __syncthreads();

    int jlo = (t >= WINW - 1) ? t - (WINW - 1) : 0;
    int nj  = t - jlo + 1;
    size_t ebbase = (size_t)(e * NB + b) * NL * DD;
    const __half* Kb = g_K + ebbase;

    {
        const float* kb = g_kbar + (size_t)(e * NB + b) * DD + h*64 + lane*2;
        float q0 = qs[h*64 + lane*2], q1 = qs[h*64 + lane*2 + 1];
        float p = q0 * kb[0] + q1 * kb[1];
#pragma unroll
        for (int off = 16; off; off >>= 1) p += __shfl_xor_sync(0xffffffffu, p, off);
        if (lane == 0) mh[h] = p * 0.125f;
    }

    int j2 = lane >> 1, half = lane & 1;
    const float* qr = &qs[h*64 + half*32];
    int ntile = (nj + 15) >> 4;
    for (int tt = 0; tt < ntile; tt++) {
        int j0 = tt << 4;
        int rows = nj - j0; if (rows > 16) rows = 16;
        for (int v = tid; v < rows * 96; v += 384) {
            int r = v / 96, c8 = v % 96;
            *(float4*)&ks[r][c8 * 8] = *(const float4*)(Kb + (size_t)(jlo + j0 + r) * DD + c8 * 8);
        }
        __syncthreads();
        const __half2* k2 = (const __half2*)&ks[j2][h*64 + half*32];
        float s = 0.f;
#pragma unroll
        for (int i = 0; i < 16; i++) {
            float2 kf = __half22float2(k2[i]);
            s += qr[2*i] * kf.x + qr[2*i+1] * kf.y;
        }
        s += __shfl_xor_sync(0xffffffffu, s, 1);
        if (half == 0 && j2 < rows) sc[h][j0 + j2] = s * 0.125f;
        __syncthreads();
    }

    float m = mh[h];
    float mx = -1e30f;
    for (int jj = lane; jj < nj; jj += 32) {
        float sv = sc[h][jj];
        float sig = 1.f / (1.f + __expf(-sv));
        float sp = sv + 0.1f * sv - 0.1f * sig * sig - 0.1f * fabsf(sv - m);
        sc[h][jj] = sp;
        mx = fmaxf(mx, sp);
    }
#pragma unroll
    for (int off = 16; off; off >>= 1) mx = fmaxf(mx, __shfl_xor_sync(0xffffffffu, mx, off));
    float sum = 0.f;
    for (int jj = lane; jj < nj; jj += 32) {
        float pexp = __expf(sc[h][jj] - mx);
        sc[h][jj] = pexp;
        sum += pexp;
    }
#pragma unroll
    for (int off = 16; off; off >>= 1) sum += __shfl_xor_sync(0xffffffffu, sum, off);
    if (lane == 0) invs[h] = 1.f / sum;
    __syncthreads();

    const __half* Vb = g_V + ebbase;
    for (int od = tid; od < DD; od += 384) {
        int hh = od >> 6;
        const __half* vb = Vb + (size_t)jlo * DD + od;
        float a0 = 0.f, a1 = 0.f, a2 = 0.f, a3 = 0.f;
        int j = 0;
        for (; j + 4 <= nj; j += 4) {
            a0 += sc[hh][j+0] * __half2float(vb[(size_t)(j+0)*DD]);
            a1 += sc[hh][j+1] * __half2float(vb[(size_t)(j+1)*DD]);
            a2 += sc[hh][j+2] * __half2float(vb[(size_t)(j+2)*DD]);
            a3 += sc[hh][j+3] * __half2float(vb[(size_t)(j+3)*DD]);
        }
        for (; j < nj; j++) a0 += sc[hh][j] * __half2float(vb[(size_t)j*DD]);
        g_attnh[(size_t)token * DD + od] = __float2half_rn((a0 + a1 + a2 + a3) * invs[hh]);
    }
}

// ---------------- launch ----------------
extern "C" void kernel_launch(void* const* d_in, const int* in_sizes, int n_in,
                              void* d_out, int out_size) {
    const float* x      = (const float*)d_in[0];
    const float* gate_w = (const float*)d_in[1];
    const float* q_w    = (const float*)d_in[2];
    const float* k_w    = (const float*)d_in[3];
    const float* v_w    = (const float*)d_in[4];
    const float* w1     = (const float*)d_in[5];
    const float* vg     = (const float*)d_in[6];
    const float* w2     = (const float*)d_in[7];
    const float* out_w  = (const float*)d_in[8];
    float* out = (float*)d_out;

    void *pK, *pV, *pQ, *pXH, *pAH, *pHh, *pYh, *pS, *pO;
    void *pqT, *pkT, *pvT, *pw1T, *pvgT, *pw2T, *poT;
    cudaGetSymbolAddress(&pK, g_K);
    cudaGetSymbolAddress(&pV, g_V);
    cudaGetSymbolAddress(&pQ, g_Q);
    cudaGetSymbolAddress(&pXH, g_xh);
    cudaGetSymbolAddress(&pAH, g_attnh);
    cudaGetSymbolAddress(&pHh, g_Hh);
    cudaGetSymbolAddress(&pYh, g_Yh);
    cudaGetSymbolAddress(&pS, g_sorted);
    cudaGetSymbolAddress(&pO, g_offs);
    cudaGetSymbolAddress(&pqT, g_qT);
    cudaGetSymbolAddress(&pkT, g_kT);
    cudaGetSymbolAddress(&pvT, g_vT);
    cudaGetSymbolAddress(&pw1T, g_w1T);
    cudaGetSymbolAddress(&pvgT, g_vgT);
    cudaGetSymbolAddress(&pw2T, g_w2T);
    cudaGetSymbolAddress(&poT, g_outT);
    const int* sortedp = (const int*)pS;
    const int* offsp   = (const int*)pO;

    const int SM_B = 4 * STG_AB;   // 81920 B
    cudaFuncSetAttribute(gemm_h,      cudaFuncAttributeMaxDynamicSharedMemorySize, SM_B);
    cudaFuncSetAttribute(gemm_swiglu, cudaFuncAttributeMaxDynamicSharedMemorySize, SM_B);

    // weight transposes + fp16 convert -> [N][K]  (64k x 32n tiles, half2 writes)
    transposeh_k<<<dim3(24, 12, NE), dim3(32, 8)>>>(q_w,   (__half*)pqT,  DD, DD);
    transposeh_k<<<dim3(24, 12, NE), dim3(32, 8)>>>(k_w,   (__half*)pkT,  DD, DD);
    transposeh_k<<<dim3(24, 12, NE), dim3(32, 8)>>>(v_w,   (__half*)pvT,  DD, DD);
    transposeh_k<<<dim3(96, 12, NE), dim3(32, 8)>>>(w1,    (__half*)pw1T, DD, FF);
    transposeh_k<<<dim3(96, 12, NE), dim3(32, 8)>>>(vg,    (__half*)pvgT, DD, FF);
    transposeh_k<<<dim3(24, 48, NE), dim3(32, 8)>>>(w2,    (__half*)pw2T, FF, DD);
    transposeh_k<<<dim3(24, 12, 1),  dim3(32, 8)>>>(out_w, (__half*)poT,  DD, DD);

    xconvh_k<<<(NTOK * DD) / 256, 256>>>(x, (__half*)pXH);
    init_k<<<1, 32>>>();
    router_k<<<NTOK / 8, 256>>>(x, gate_w);
    offs_k<<<1, 32>>>(out, (long long)out_size);
    scatter_k<<<NTOK / 256, 256>>>();
    xbar_k<<<NB, 256>>>(x);
    kbar2_k<<<NE, 256>>>(k_w);

    SlotH sK  = { (const __half*)pkT,  pK,  (unsigned long long)DD*DD, (unsigned long long)NTOK*DD, 0, 1 };
    SlotH sV  = { (const __half*)pvT,  pV,  (unsigned long long)DD*DD, (unsigned long long)NTOK*DD, 0, 1 };
    SlotH sQ  = { (const __half*)pqT,  pQ,  (unsigned long long)DD*DD, 0ull, 1, 0 };
    SlotH sW2 = { (const __half*)pw2T, pYh, (unsigned long long)FF*DD, 0ull, 1, 1 };
    SlotH sOW = { (const __half*)poT,  d_out, 0ull, 0ull, 0, 0 };

    // K, V (dense, fp16 out) + Q (gathered, fp32 out) in one launch
    gemm_h<<<dim3(18, 16, 8), 256, SM_B>>>(
        (const __half*)pXH, DD, DD, 6, sK, sV, sQ, sortedp, offsp);

    attn_k<<<NTOK, 384>>>();

    // fused SwiGLU dual GEMM -> fp16 (no z round-trip)
    gemm_swiglu<<<dim3(FF/64, 16, 8), 256, SM_B>>>(
        (const __half*)pAH, (const __half*)pw1T, (const __half*)pvgT,
        (__half*)pHh, sortedp, offsp);

    // down projection (gathered, K=3072) -> fp16
    gemm_h<<<dim3(6, 16, 8), 256, SM_B>>>(
        (const __half*)pHh, DD, FF, 6, sW2, sW2, sW2, sortedp, offsp);

    // final output projection (dense) -> fp32 d_out
    gemm_h<<<dim3(6, 16, 1), 256, SM_B>>>(
        (const __half*)pYh, DD, DD, 6, sOW, sOW, sOW, sortedp, offsp);
}

// round 16
// speedup vs baseline: 1.4453x; 1.0342x over previous
#include <cuda_runtime.h>
#include <cuda_fp16.h>
#include <math.h>
#include <stdint.h>

// ---------------- problem constants ----------------
#define DD    768
#define FF    3072
#define NE    8
#define NB    2
#define NL    1024
#define NTOK  2048
#define NH    12
#define HD    64
#define WINW  128
#define NOUT  (NTOK*DD)

// ---------------- device scratch ----------------
__device__ __half g_K[NE*NTOK*DD];
__device__ __half g_V[NE*NTOK*DD];
__device__ float  g_Q[NTOK*DD];
__device__ __half g_xh[NTOK*DD];
__device__ __half g_attnh[NTOK*DD];
__device__ __half g_Hh[NTOK*FF];
__device__ __half g_Yh[NTOK*DD];
__device__ float  g_xbar[NB*DD];
__device__ float  g_kbar[NE*NB*DD];
__device__ int    g_idx[NTOK];
__device__ int    g_sorted[NTOK];
__device__ int    g_counts[NE];
__device__ int    g_cursor[NE];
__device__ int    g_offs[NE+1];
__device__ float  g_Psum[NE];
// transposed fp16 weights [N][K] per expert
__device__ __half g_qT[NE*DD*DD];
__device__ __half g_kT[NE*DD*DD];
__device__ __half g_vT[NE*DD*DD];
__device__ __half g_w1T[NE*DD*FF];
__device__ __half g_vgT[NE*DD*FF];
__device__ __half g_w2T[NE*FF*DD];
__device__ __half g_outT[DD*DD];

// ---------------- PTX helpers ----------------
__device__ __forceinline__ uint32_t smem_u32(const void* p) {
    uint32_t a;
    asm("{ .reg .u64 t; cvta.to.shared.u64 t, %1; cvt.u32.u64 %0, t; }" : "=r"(a) : "l"(p));
    return a;
}
__device__ __forceinline__ void cp16(uint32_t s, const void* g) {
    asm volatile("cp.async.cg.shared.global [%0], [%1], 16;" :: "r"(s), "l"(g) : "memory");
}
__device__ __forceinline__ void cp_commit() {
    asm volatile("cp.async.commit_group;" ::: "memory");
}
template<int N> __device__ __forceinline__ void cp_wait() {
    asm volatile("cp.async.wait_group %0;" :: "n"(N) : "memory");
}
__device__ __forceinline__ void mma16(float* c, const uint32_t* a, const uint32_t* b) {
    asm volatile("mma.sync.aligned.m16n8k16.row.col.f32.f16.f16.f32 "
        "{%0,%1,%2,%3}, {%4,%5,%6,%7}, {%8,%9}, {%0,%1,%2,%3};"
        : "+f"(c[0]), "+f"(c[1]), "+f"(c[2]), "+f"(c[3])
        : "r"(a[0]), "r"(a[1]), "r"(a[2]), "r"(a[3]), "r"(b[0]), "r"(b[1]));
}
__device__ __forceinline__ void ldsm4(uint32_t* r, uint32_t addr) {
    asm volatile("ldmatrix.sync.aligned.m8n8.x4.shared.b16 {%0,%1,%2,%3}, [%4];"
        : "=r"(r[0]), "=r"(r[1]), "=r"(r[2]), "=r"(r[3]) : "r"(addr));
}

// ---------------- init / router / offs / scatter ----------------
__global__ void init_k() {
    int t = threadIdx.x;
    if (t < NE) { g_counts[t] = 0; g_Psum[t] = 0.f; }
}

__global__ __launch_bounds__(256) void router_k(const float* __restrict__ x,
                                                const float* __restrict__ gw) {
    int gtid = blockIdx.x * 256 + threadIdx.x;
    int tok  = gtid >> 5;
    int lane = gtid & 31;
    if (tok >= NTOK) return;
    const float* xr = x + (size_t)tok * DD;
    float acc[NE];
#pragma unroll
    for (int e = 0; e < NE; e++) acc[e] = 0.f;
    for (int d = lane; d < DD; d += 32) {
        float xv = xr[d];
        const float* g = gw + (size_t)d * NE;
#pragma unroll
        for (int e = 0; e < NE; e++) acc[e] += xv * g[e];
    }
#pragma unroll
    for (int e = 0; e < NE; e++)
#pragma unroll
        for (int off = 16; off; off >>= 1)
            acc[e] += __shfl_xor_sync(0xffffffffu, acc[e], off);
    if (lane == 0) {
        float l[NE]; float mx = -1e30f;
#pragma unroll
        for (int e = 0; e < NE; e++) { l[e] = acc[e] * 0.5f; mx = fmaxf(mx, l[e]); }
        int best = 0; float bv = l[0];
#pragma unroll
        for (int e = 1; e < NE; e++) if (l[e] > bv) { bv = l[e]; best = e; }
        g_idx[tok] = best;
        atomicAdd(&g_counts[best], 1);
        float p[NE]; float se = 0.f;
#pragma unroll
        for (int e = 0; e < NE; e++) { p[e] = expf(l[e] - mx); se += p[e]; }
        float inv = 1.f / se;
#pragma unroll
        for (int e = 0; e < NE; e++) atomicAdd(&g_Psum[e], p[e] * inv);
    }
}

__global__ void offs_k(float* __restrict__ dout, long long out_size) {
    if (threadIdx.x == 0 && blockIdx.x == 0) {
        int o = 0;
        for (int e = 0; e < NE; e++) { g_offs[e] = o; g_cursor[e] = o; o += g_counts[e]; }
        g_offs[NE] = o;
        float aux = 0.f;
        for (int e = 0; e < NE; e++) aux += (float)g_counts[e] * g_Psum[e];
        aux *= (float)NE / ((float)NTOK * (float)NTOK);
        if (out_size > (long long)NOUT) dout[NOUT] = aux;
    }
}

__global__ void scatter_k() {
    int t = blockIdx.x * 256 + threadIdx.x;
    if (t < NTOK) {
        int e = g_idx[t];
        int p = atomicAdd(&g_cursor[e], 1);
        g_sorted[p] = t;
    }
}

// ---------------- x -> fp16 copy ----------------
__global__ __launch_bounds__(256) void xconvh_k(const float* __restrict__ x, __half* __restrict__ xh) {
    int i = blockIdx.x * 256 + threadIdx.x;
    if (i < NTOK * DD) xh[i] = __float2half_rn(x[i]);
}

// ---------------- x column means per batch ----------------
__global__ __launch_bounds__(256) void xbar_k(const float* __restrict__ x) {
    int b = blockIdx.x;
    for (int d = threadIdx.x; d < DD; d += 256) {
        float s = 0.f;
        const float* xb = x + (size_t)b * NL * DD + d;
        for (int j = 0; j < NL; j++) s += xb[(size_t)j * DD];
        g_xbar[b * DD + d] = s * (1.f / (float)NL);
    }
}

// ---------------- kbar[e,b,:] = xbar[b,:] @ k_w[e] ----------------
__global__ __launch_bounds__(256) void kbar2_k(const float* __restrict__ k_w) {
    int e = blockIdx.x;
    __shared__ float xs[NB * DD];
    for (int i = threadIdx.x; i < NB * DD; i += 256) xs[i] = g_xbar[i];
    __syncthreads();
    const float* W = k_w + (size_t)e * DD * DD;
    for (int d = threadIdx.x; d < DD; d += 256) {
        float a0 = 0.f, a1 = 0.f;
        for (int dk = 0; dk < DD; dk++) {
            float w = W[(size_t)dk * DD + d];
            a0 += xs[dk] * w;
            a1 += xs[DD + dk] * w;
        }
        g_kbar[(e * NB + 0) * DD + d] = a0;
        g_kbar[(e * NB + 1) * DD + d] = a1;
    }
}

// ---------------- weight transpose + fp16 convert: src[e][K][N] -> dst[e][N][K] half ----------------
// Multi-tensor: blockIdx.z selects (tensor = z/NE, expert = z%NE). 64k x 32n tile, half2 writes.
__global__ __launch_bounds__(256) void transposeh_k(
    const float* s0, const float* s1, const float* s2,
    __half* d0, __half* d1, __half* d2, int K, int N) {
    __shared__ float t[64][33];
    int which = blockIdx.z / NE, e = blockIdx.z % NE;
    const float* sb = (which == 0) ? s0 : (which == 1) ? s1 : s2;
    __half* db = (which == 0) ? d0 : (which == 1) ? d1 : d2;
    const float* s = sb + (size_t)e * K * N;
    __half* d = db + (size_t)e * K * N;
    int n0 = blockIdx.x * 32, k0 = blockIdx.y * 64;
    int tx = threadIdx.x, ty = threadIdx.y;
#pragma unroll
    for (int i = 0; i < 64; i += 8)
        t[ty + i][tx] = s[(size_t)(k0 + ty + i) * N + n0 + tx];
    __syncthreads();
#pragma unroll
    for (int i = 0; i < 32; i += 8) {
        int r = ty + i;
        __half2 h = __floats2half2_rn(t[2 * tx][r], t[2 * tx + 1][r]);
        *(__half2*)(d + (size_t)(n0 + r) * K + k0 + 2 * tx) = h;
    }
}

// ---------------- slot descriptor ----------------
struct SlotH {
    const __half* B;
    void* C;
    unsigned long long strideB;
    unsigned long long strideC;
    int gather;
    int outh;                   // 1 = write __half, 0 = write float
};

// ---------------- fp16 mma.sync GEMM (m16n8k16), single-B, 128x128 ----------------
#define STG_A  10240
#define STG_AB 20480
__global__ __launch_bounds__(256, 2) void gemm_h(
    const __half* __restrict__ A, int ldc, int K, int nbx,
    SlotH s0, SlotH s1, SlotH s2,
    const int* __restrict__ sorted, const int* __restrict__ offs)
{
    extern __shared__ char smc[];
    __shared__ int rs[128];
    int which = blockIdx.x / nbx;
    int n0 = (blockIdx.x - which * nbx) * 128;
    const __half* Bb; void* Cb; unsigned long long sB, sC; int gat, outh;
    if (which == 0)      { Bb = s0.B; Cb = s0.C; sB = s0.strideB; sC = s0.strideC; gat = s0.gather; outh = s0.outh; }
    else if (which == 1) { Bb = s1.B; Cb = s1.C; sB = s1.strideB; sC = s1.strideC; gat = s1.gather; outh = s1.outh; }
    else                 { Bb = s2.B; Cb = s2.C; sB = s2.strideB; sC = s2.strideC; gat = s2.gather; outh = s2.outh; }
    int e = blockIdx.z;
    int cnt; const int* rmap;
    if (gat) { int st0 = offs[e]; cnt = offs[e + 1] - st0; rmap = sorted + st0; }
    else     { cnt = NTOK; rmap = nullptr; }
    int m0 = blockIdx.y * 128;
    if (m0 >= cnt) return;
    const __half* Be = Bb + sB * (size_t)e;

    int tid = threadIdx.x;
    if (tid < 128) {
        int ra = m0 + tid;
        int row = (ra < cnt) ? ra : (cnt - 1);
        rs[tid] = rmap ? rmap[row] : row;
    }
    __syncthreads();

    uint32_t sbase = smem_u32(smc);

    const __half* aptr[2]; const __half* bptr[2];
    uint32_t soA[2], soB[2];
#pragma unroll
    for (int i = 0; i < 2; i++) {
        int f = i * 256 + tid;
        int row = f >> 2, c = f & 3;
        aptr[i] = A + (size_t)rs[row] * K + c * 8;
        bptr[i] = Be + (size_t)(n0 + row) * K + c * 8;
        uint32_t so = (uint32_t)(row * 80 + c * 16);
        soA[i] = sbase + so;
        soB[i] = sbase + (uint32_t)STG_A + so;
    }

    int lane = tid & 31, wid = tid >> 5;
    int g = lane >> 2, t4 = lane & 3;
    int wm = wid & 1, wn = wid >> 1;
    int mb0 = wm * 64, nb0 = wn * 32;
    int lr = lane & 7, lg = lane >> 3;

    float c1[4][4][4];
#pragma unroll
    for (int mf = 0; mf < 4; mf++)
#pragma unroll
        for (int nf = 0; nf < 4; nf++)
#pragma unroll
            for (int q = 0; q < 4; q++) c1[mf][nf][q] = 0.f;

    int NIT = K >> 5;

    auto load_tile = [&](int it, int st) {
        uint32_t sb = (uint32_t)st * STG_AB;
        int k0 = it << 5;
#pragma unroll
        for (int i = 0; i < 2; i++) cp16(soA[i] + sb, aptr[i] + k0);
#pragma unroll
        for (int i = 0; i < 2; i++) cp16(soB[i] + sb, bptr[i] + k0);
        cp_commit();
    };

    load_tile(0, 0);
    load_tile(1, 1);
    load_tile(2, 2);

    uint32_t aRowOff = (uint32_t)((lr + (lg & 1) * 8) * 80 + (lg >> 1) * 16);
    uint32_t bRowOff = (uint32_t)((lr + (lg >> 1) * 8) * 80 + (lg & 1) * 16);

    for (int it = 0; it < NIT; it++) {
        int rem = NIT - 1 - it;
        if (rem >= 2) cp_wait<2>(); else if (rem == 1) cp_wait<1>(); else cp_wait<0>();
        __syncthreads();
        int st = it & 3;
        uint32_t Ast = sbase + (uint32_t)st * STG_AB;
        uint32_t Bst = Ast + (uint32_t)STG_A;

#pragma unroll
        for (int kk = 0; kk < 32; kk += 16) {
            uint32_t kbyte = (uint32_t)(kk * 2);
            uint32_t af[4][4];
#pragma unroll
            for (int mf = 0; mf < 4; mf++)
                ldsm4(af[mf], Ast + (uint32_t)((mb0 + mf * 16) * 80) + aRowOff + kbyte);
            uint32_t bf[2][4];
#pragma unroll
            for (int np = 0; np < 2; np++)
                ldsm4(bf[np], Bst + (uint32_t)((nb0 + np * 16) * 80) + bRowOff + kbyte);
#pragma unroll
            for (int mf = 0; mf < 4; mf++)
#pragma unroll
                for (int nf = 0; nf < 4; nf++)
                    mma16(c1[mf][nf], af[mf], &bf[nf >> 1][(nf & 1) * 2]);
        }
        if (it + 3 < NIT) load_tile(it + 3, (it + 3) & 3);
    }

#pragma unroll
    for (int mf = 0; mf < 4; mf++) {
        int lr0 = mb0 + mf * 16 + g;
        int lr1 = lr0 + 8;
        bool v0 = (m0 + lr0) < cnt;
        bool v1 = (m0 + lr1) < cnt;
        size_t o0 = (size_t)rs[lr0] * ldc + n0 + nb0;
        size_t o1 = (size_t)rs[lr1] * ldc + n0 + nb0;
#pragma unroll
        for (int nf = 0; nf < 4; nf++) {
            int co = nf * 8 + 2 * t4;
            float a0 = c1[mf][nf][0], a1 = c1[mf][nf][1];
            float a2 = c1[mf][nf][2], a3 = c1[mf][nf][3];
            if (outh) {
                __half* C = (__half*)Cb + sC * (size_t)e;
                if (v0) *(__half2*)(C + o0 + co) = __floats2half2_rn(a0, a1);
                if (v1) *(__half2*)(C + o1 + co) = __floats2half2_rn(a2, a3);
            } else {
                float* C = (float*)Cb + sC * (size_t)e;
                if (v0) *(float2*)(C + o0 + co) = make_float2(a0, a1);
                if (v1) *(float2*)(C + o1 + co) = make_float2(a2, a3);
            }
        }
    }
}

// ---------------- fp16 GEMM, block tile 64x128x32 (for grid-starved tail GEMMs) ----------------
// 8 warps, all 1 m-row of warps: warp wn covers n [wn*16, wn*16+16), m 0..63.
// Stage = A(64x80=5120) + B(128x80=10240) = 15360; 4 stages = 61440 B; 2 CTAs/SM.
#define STG64_A  5120
#define STG64_AB 15360
__global__ __launch_bounds__(256, 2) void gemm_h64(
    const __half* __restrict__ A, int ldc, int K,
    SlotH s0,
    const int* __restrict__ sorted, const int* __restrict__ offs)
{
    extern __shared__ char smc[];
    __shared__ int rs[64];
    int n0 = blockIdx.x * 128;
    const __half* Bb = s0.B; void* Cb = s0.C;
    unsigned long long sB = s0.strideB, sC = s0.strideC;
    int gat = s0.gather, outh = s0.outh;
    int e = blockIdx.z;
    int cnt; const int* rmap;
    if (gat) { int st0 = offs[e]; cnt = offs[e + 1] - st0; rmap = sorted + st0; }
    else     { cnt = NTOK; rmap = nullptr; }
    int m0 = blockIdx.y * 64;
    if (m0 >= cnt) return;
    const __half* Be = Bb + sB * (size_t)e;

    int tid = threadIdx.x;
    if (tid < 64) {
        int ra = m0 + tid;
        int row = (ra < cnt) ? ra : (cnt - 1);
        rs[tid] = rmap ? rmap[row] : row;
    }
    __syncthreads();

    uint32_t sbase = smem_u32(smc);

    // A: 64 rows x 4 chunks = 256 slots -> 1 cp16/thread.
    // B: 128 rows x 4 chunks = 512 -> 2 cp16/thread.
    const __half* aptr; const __half* bptr[2];
    uint32_t soA, soB[2];
    {
        int row = tid >> 2, c = tid & 3;
        aptr = A + (size_t)rs[row] * K + c * 8;
        soA  = sbase + (uint32_t)(row * 80 + c * 16);
    }
#pragma unroll
    for (int i = 0; i < 2; i++) {
        int f = i * 256 + tid;
        int row = f >> 2, c = f & 3;
        bptr[i] = Be + (size_t)(n0 + row) * K + c * 8;
        soB[i]  = sbase + (uint32_t)STG64_A + (uint32_t)(row * 80 + c * 16);
    }

    int lane = tid & 31, wid = tid >> 5;
    int g = lane >> 2, t4 = lane & 3;
    int nb0 = wid * 16;
    int lr = lane & 7, lg = lane >> 3;

    float c1[4][2][4];
#pragma unroll
    for (int mf = 0; mf < 4; mf++)
#pragma unroll
        for (int nf = 0; nf < 2; nf++)
#pragma unroll
            for (int q = 0; q < 4; q++) c1[mf][nf][q] = 0.f;

    int NIT = K >> 5;

    auto load_tile = [&](int it, int st) {
        uint32_t sb = (uint32_t)st * STG64_AB;
        int k0 = it << 5;
        cp16(soA + sb, aptr + k0);
#pragma unroll
        for (int i = 0; i < 2; i++) cp16(soB[i] + sb, bptr[i] + k0);
        cp_commit();
    };

    load_tile(0, 0);
    load_tile(1, 1);
    load_tile(2, 2);

    uint32_t aRowOff = (uint32_t)((lr + (lg & 1) * 8) * 80 + (lg >> 1) * 16);
    uint32_t bRowOff = (uint32_t)((lr + (lg >> 1) * 8) * 80 + (lg & 1) * 16);

    for (int it = 0; it < NIT; it++) {
        int rem = NIT - 1 - it;
        if (rem >= 2) cp_wait<2>(); else if (rem == 1) cp_wait<1>(); else cp_wait<0>();
        __syncthreads();
        int st = it & 3;
        uint32_t Ast = sbase + (uint32_t)st * STG64_AB;
        uint32_t Bst = Ast + (uint32_t)STG64_A;

#pragma unroll
        for (int kk = 0; kk < 32; kk += 16) {
            uint32_t kbyte = (uint32_t)(kk * 2);
            uint32_t af[4][4];
#pragma unroll
            for (int mf = 0; mf < 4; mf++)
                ldsm4(af[mf], Ast + (uint32_t)((mf * 16) * 80) + aRowOff + kbyte);
            uint32_t bf[4];
            ldsm4(bf, Bst + (uint32_t)(nb0 * 80) + bRowOff + kbyte);
#pragma unroll
            for (int mf = 0; mf < 4; mf++)
#pragma unroll
                for (int nf = 0; nf < 2; nf++)
                    mma16(c1[mf][nf], af[mf], &bf[nf * 2]);
        }
        if (it + 3 < NIT) load_tile(it + 3, (it + 3) & 3);
    }

#pragma unroll
    for (int mf = 0; mf < 4; mf++) {
        int lr0 = mf * 16 + g;
        int lr1 = lr0 + 8;
        bool v0 = (m0 + lr0) < cnt;
        bool v1 = (m0 + lr1) < cnt;
        size_t o0 = (size_t)rs[lr0] * ldc + n0 + nb0;
        size_t o1 = (size_t)rs[lr1] * ldc + n0 + nb0;
#pragma unroll
        for (int nf = 0; nf < 2; nf++) {
            int co = nf * 8 + 2 * t4;
            float a0 = c1[mf][nf][0], a1 = c1[mf][nf][1];
            float a2 = c1[mf][nf][2], a3 = c1[mf][nf][3];
            if (outh) {
                __half* C = (__half*)Cb + sC * (size_t)e;
                if (v0) *(__half2*)(C + o0 + co) = __floats2half2_rn(a0, a1);
                if (v1) *(__half2*)(C + o1 + co) = __floats2half2_rn(a2, a3);
            } else {
                float* C = (float*)Cb + sC * (size_t)e;
                if (v0) *(float2*)(C + o0 + co) = make_float2(a0, a1);
                if (v1) *(float2*)(C + o1 + co) = make_float2(a2, a3);
            }
        }
    }
}

// ---------------- fused SwiGLU dual GEMM: h = silu(A@w1) * (A@vg) ----------------
#define STG_B2 5120
__global__ __launch_bounds__(256, 2) void gemm_swiglu(
    const __half* __restrict__ A,
    const __half* __restrict__ W1, const __half* __restrict__ VG,
    __half* __restrict__ C,
    const int* __restrict__ sorted, const int* __restrict__ offs)
{
    extern __shared__ char smc[];
    __shared__ int rs[128];
    const int K = DD, ldc = FF;
    int n0 = blockIdx.x * 64;
    int e = blockIdx.z;
    int st0 = offs[e];
    int cnt = offs[e + 1] - st0;
    const int* rmap = g_sorted + st0;
    int m0 = blockIdx.y * 128;
    if (m0 >= cnt) return;
    const __half* B1e = W1 + (size_t)e * DD * FF;
    const __half* B2e = VG + (size_t)e * DD * FF;

    int tid = threadIdx.x;
    if (tid < 128) {
        int ra = m0 + tid;
        int row = (ra < cnt) ? ra : (cnt - 1);
        rs[tid] = rmap ? rmap[row] : row;
    }
    __syncthreads();

    uint32_t sbase = smem_u32(smc);

    const __half* aptr[2]; const __half* b1p; const __half* b2p;
    uint32_t soA[2], soB;
#pragma unroll
    for (int i = 0; i < 2; i++) {
        int f = i * 256 + tid;
        int row = f >> 2, c = f & 3;
        aptr[i] = A + (size_t)rs[row] * K + c * 8;
        soA[i]  = sbase + (uint32_t)(row * 80 + c * 16);
    }
    {
        int row = tid >> 2, c = tid & 3;
        b1p = B1e + (size_t)(n0 + row) * K + c * 8;
        b2p = B2e + (size_t)(n0 + row) * K + c * 8;
        soB = sbase + (uint32_t)STG_A + (uint32_t)(row * 80 + c * 16);
    }

    int lane = tid & 31, wid = tid >> 5;
    int g = lane >> 2, t4 = lane & 3;
    int wm = wid & 1, wn = wid >> 1;
    int mb0 = wm * 64, nb0 = wn * 16;
    int lr = lane & 7, lg = lane >> 3;

    float c1[4][2][4], c2[4][2][4];
#pragma unroll
    for (int mf = 0; mf < 4; mf++)
#pragma unroll
        for (int nf = 0; nf < 2; nf++)
#pragma unroll
            for (int q = 0; q < 4; q++) { c1[mf][nf][q] = 0.f; c2[mf][nf][q] = 0.f; }

    int NIT = K >> 5;

    auto load_tile = [&](int it, int st) {
        uint32_t sb = (uint32_t)st * STG_AB;
        int k0 = it << 5;
#pragma unroll
        for (int i = 0; i < 2; i++) cp16(soA[i] + sb, aptr[i] + k0);
        cp16(soB + sb, b1p + k0);
        cp16(soB + sb + (uint32_t)STG_B2, b2p + k0);
        cp_commit();
    };

    load_tile(0, 0);
    load_tile(1, 1);
    load_tile(2, 2);

    uint32_t aRowOff = (uint32_t)((lr + (lg & 1) * 8) * 80 + (lg >> 1) * 16);
    uint32_t bRowOff = (uint32_t)((lr + (lg >> 1) * 8) * 80 + (lg & 1) * 16);

    for (int it = 0; it < NIT; it++) {
        int rem = NIT - 1 - it;
        if (rem >= 2) cp_wait<2>(); else if (rem == 1) cp_wait<1>(); else cp_wait<0>();
        __syncthreads();
        int st = it & 3;
        uint32_t Ast = sbase + (uint32_t)st * STG_AB;
        uint32_t B1st = Ast + (uint32_t)STG_A;
        uint32_t B2st = B1st + (uint32_t)STG_B2;

#pragma unroll
        for (int kk = 0; kk < 32; kk += 16) {
            uint32_t kbyte = (uint32_t)(kk * 2);
            uint32_t af[4][4];
#pragma unroll
            for (int mf = 0; mf < 4; mf++)
                ldsm4(af[mf], Ast + (uint32_t)((mb0 + mf * 16) * 80) + aRowOff + kbyte);
            uint32_t b1f[4], b2f[4];
            ldsm4(b1f, B1st + (uint32_t)(nb0 * 80) + bRowOff + kbyte);
            ldsm4(b2f, B2st + (uint32_t)(nb0 * 80) + bRowOff + kbyte);
#pragma unroll
            for (int mf = 0; mf < 4; mf++)
#pragma unroll
                for (int nf = 0; nf < 2; nf++) {
                    mma16(c1[mf][nf], af[mf], &b1f[nf * 2]);
                    mma16(c2[mf][nf], af[mf], &b2f[nf * 2]);
                }
        }
        if (it + 3 < NIT) load_tile(it + 3, (it + 3) & 3);
    }

#pragma unroll
    for (int mf = 0; mf < 4; mf++) {
        int lr0 = mb0 + mf * 16 + g;
        int lr1 = lr0 + 8;
        bool v0 = (m0 + lr0) < cnt;
        bool v1 = (m0 + lr1) < cnt;
        __half* p0 = C + (size_t)rs[lr0] * ldc + n0 + nb0;
        __half* p1 = C + (size_t)rs[lr1] * ldc + n0 + nb0;
#pragma unroll
        for (int nf = 0; nf < 2; nf++) {
            int co = nf * 8 + 2 * t4;
            float z0 = c1[mf][nf][0], z1 = c1[mf][nf][1];
            float z2 = c1[mf][nf][2], z3 = c1[mf][nf][3];
            float h0 = z0 / (1.f + expf(-z0)) * c2[mf][nf][0];
            float h1 = z1 / (1.f + expf(-z1)) * c2[mf][nf][1];
            float h2 = z2 / (1.f + expf(-z2)) * c2[mf][nf][2];
            float h3 = z3 / (1.f + expf(-z3)) * c2[mf][nf][3];
            if (v0) *(__half2*)(p0 + co) = __floats2half2_rn(h0, h1);
            if (v1) *(__half2*)(p1 + co) = __floats2half2_rn(h2, h3);
        }
    }
}

// ---------------- sliding-window attention with Reynolds modulation ----------------
#define KHPAD 776
__global__ __launch_bounds__(384) void attn_k() {
    int token = blockIdx.x;
    int b = token >> 10;
    int t = token & (NL - 1);
    int e = g_idx[token];

    __shared__ float qs[DD];
    __shared__ float sc[NH][WINW + 4];
    __shared__ float mh[NH], invs[NH];
    __shared__ __half ks[16][KHPAD];

    int tid = threadIdx.x, lane = tid & 31, h = tid >> 5;
    for (int d = tid; d < DD; d += 384) qs[d] = g_Q[(size_t)token * DD + d];
    __syncthreads();

    int jlo = (t >= WINW - 1) ? t - (WINW - 1) : 0;
    int nj  = t - jlo + 1;
    size_t ebbase = (size_t)(e * NB + b) * NL * DD;
    const __half* Kb = g_K + ebbase;

    {
        const float* kb = g_kbar + (size_t)(e * NB + b) * DD + h*64 + lane*2;
        float q0 = qs[h*64 + lane*2], q1 = qs[h*64 + lane*2 + 1];
        float p = q0 * kb[0] + q1 * kb[1];
#pragma unroll
        for (int off = 16; off; off >>= 1) p += __shfl_xor_sync(0xffffffffu, p, off);
        if (lane == 0) mh[h] = p * 0.125f;
    }

    int j2 = lane >> 1, half = lane & 1;
    const float* qr = &qs[h*64 + half*32];
    int ntile = (nj + 15) >> 4;
    for (int tt = 0; tt < ntile; tt++) {
        int j0 = tt << 4;
        int rows = nj - j0; if (rows > 16) rows = 16;
        for (int v = tid; v < rows * 96; v += 384) {
            int r = v / 96, c8 = v % 96;
            *(float4*)&ks[r][c8 * 8] = *(const float4*)(Kb + (size_t)(jlo + j0 + r) * DD + c8 * 8);
        }
        __syncthreads();
        const __half2* k2 = (const __half2*)&ks[j2][h*64 + half*32];
        float s = 0.f;
#pragma unroll
        for (int i = 0; i < 16; i++) {
            float2 kf = __half22float2(k2[i]);
            s += qr[2*i] * kf.x + qr[2*i+1] * kf.y;
        }
        s += __shfl_xor_sync(0xffffffffu, s, 1);
        if (half == 0 && j2 < rows) sc[h][j0 + j2] = s * 0.125f;
        __syncthreads();
    }

    float m = mh[h];
    float mx = -1e30f;
    for (int jj = lane; jj < nj; jj += 32) {
        float sv = sc[h][jj];
        float sig = 1.f / (1.f + __expf(-sv));
        float sp = sv + 0.1f * sv - 0.1f * sig * sig - 0.1f * fabsf(sv - m);
        sc[h][jj] = sp;
        mx = fmaxf(mx, sp);
    }
#pragma unroll
    for (int off = 16; off; off >>= 1) mx = fmaxf(mx, __shfl_xor_sync(0xffffffffu, mx, off));
    float sum = 0.f;
    for (int jj = lane; jj < nj; jj += 32) {
        float pexp = __expf(sc[h][jj] - mx);
        sc[h][jj] = pexp;
        sum += pexp;
    }
#pragma unroll
    for (int off = 16; off; off >>= 1) sum += __shfl_xor_sync(0xffffffffu, sum, off);
    if (lane == 0) invs[h] = 1.f / sum;
    __syncthreads();

    const __half* Vb = g_V + ebbase;
    for (int od = tid; od < DD; od += 384) {
        int hh = od >> 6;
        const __half* vb = Vb + (size_t)jlo * DD + od;
        float a0 = 0.f, a1 = 0.f, a2 = 0.f, a3 = 0.f;
        int j = 0;
        for (; j + 4 <= nj; j += 4) {
            a0 += sc[hh][j+0] * __half2float(vb[(size_t)(j+0)*DD]);
            a1 += sc[hh][j+1] * __half2float(vb[(size_t)(j+1)*DD]);
            a2 += sc[hh][j+2] * __half2float(vb[(size_t)(j+2)*DD]);
            a3 += sc[hh][j+3] * __half2float(vb[(size_t)(j+3)*DD]);
        }
        for (; j < nj; j++) a0 += sc[hh][j] * __half2float(vb[(size_t)j*DD]);
        g_attnh[(size_t)token * DD + od] = __float2half_rn((a0 + a1 + a2 + a3) * invs[hh]);
    }
}

// ---------------- launch ----------------
extern "C" void kernel_launch(void* const* d_in, const int* in_sizes, int n_in,
                              void* d_out, int out_size) {
    const float* x      = (const float*)d_in[0];
    const float* gate_w = (const float*)d_in[1];
    const float* q_w    = (const float*)d_in[2];
    const float* k_w    = (const float*)d_in[3];
    const float* v_w    = (const float*)d_in[4];
    const float* w1     = (const float*)d_in[5];
    const float* vg     = (const float*)d_in[6];
    const float* w2     = (const float*)d_in[7];
    const float* out_w  = (const float*)d_in[8];
    float* out = (float*)d_out;

    void *pK, *pV, *pQ, *pXH, *pAH, *pHh, *pYh, *pS, *pO;
    void *pqT, *pkT, *pvT, *pw1T, *pvgT, *pw2T, *poT;
    cudaGetSymbolAddress(&pK, g_K);
    cudaGetSymbolAddress(&pV, g_V);
    cudaGetSymbolAddress(&pQ, g_Q);
    cudaGetSymbolAddress(&pXH, g_xh);
    cudaGetSymbolAddress(&pAH, g_attnh);
    cudaGetSymbolAddress(&pHh, g_Hh);
    cudaGetSymbolAddress(&pYh, g_Yh);
    cudaGetSymbolAddress(&pS, g_sorted);
    cudaGetSymbolAddress(&pO, g_offs);
    cudaGetSymbolAddress(&pqT, g_qT);
    cudaGetSymbolAddress(&pkT, g_kT);
    cudaGetSymbolAddress(&pvT, g_vT);
    cudaGetSymbolAddress(&pw1T, g_w1T);
    cudaGetSymbolAddress(&pvgT, g_vgT);
    cudaGetSymbolAddress(&pw2T, g_w2T);
    cudaGetSymbolAddress(&poT, g_outT);
    const int* sortedp = (const int*)pS;
    const int* offsp   = (const int*)pO;

    const int SM_B  = 4 * STG_AB;     // 81920 B
    const int SM_B64 = 4 * STG64_AB;  // 61440 B
    cudaFuncSetAttribute(gemm_h,      cudaFuncAttributeMaxDynamicSharedMemorySize, SM_B);
    cudaFuncSetAttribute(gemm_h64,    cudaFuncAttributeMaxDynamicSharedMemorySize, SM_B64);
    cudaFuncSetAttribute(gemm_swiglu, cudaFuncAttributeMaxDynamicSharedMemorySize, SM_B);

    // weight transposes + fp16 convert -> [N][K]  (merged multi-tensor launches)
    transposeh_k<<<dim3(24, 12, 3 * NE), dim3(32, 8)>>>(
        q_w, k_w, v_w, (__half*)pqT, (__half*)pkT, (__half*)pvT, DD, DD);
    transposeh_k<<<dim3(96, 12, 2 * NE), dim3(32, 8)>>>(
        w1, vg, nullptr, (__half*)pw1T, (__half*)pvgT, nullptr, DD, FF);
    transposeh_k<<<dim3(24, 48, NE), dim3(32, 8)>>>(
        w2, nullptr, nullptr, (__half*)pw2T, nullptr, nullptr, FF, DD);
    transposeh_k<<<dim3(24, 12, 1), dim3(32, 8)>>>(
        out_w, nullptr, nullptr, (__half*)poT, nullptr, nullptr, DD, DD);

    xconvh_k<<<(NTOK * DD) / 256, 256>>>(x, (__half*)pXH);
    init_k<<<1, 32>>>();
    router_k<<<NTOK / 8, 256>>>(x, gate_w);
    offs_k<<<1, 32>>>(out, (long long)out_size);
    scatter_k<<<NTOK / 256, 256>>>();
    xbar_k<<<NB, 256>>>(x);
    kbar2_k<<<NE, 256>>>(k_w);

    SlotH sK  = { (const __half*)pkT,  pK,  (unsigned long long)DD*DD, (unsigned long long)NTOK*DD, 0, 1 };
    SlotH sV  = { (const __half*)pvT,  pV,  (unsigned long long)DD*DD, (unsigned long long)NTOK*DD, 0, 1 };
    SlotH sQ  = { (const __half*)pqT,  pQ,  (unsigned long long)DD*DD, 0ull, 1, 0 };
    SlotH sW2 = { (const __half*)pw2T, pYh, (unsigned long long)FF*DD, 0ull, 1, 1 };
    SlotH sOW = { (const __half*)poT,  d_out, 0ull, 0ull, 0, 0 };

    // K, V (dense, fp16 out) + Q (gathered, fp32 out) in one launch
    gemm_h<<<dim3(18, 16, 8), 256, SM_B>>>(
        (const __half*)pXH, DD, DD, 6, sK, sV, sQ, sortedp, offsp);

    attn_k<<<NTOK, 384>>>();

    // fused SwiGLU dual GEMM -> fp16
    gemm_swiglu<<<dim3(FF/64, 16, 8), 256, SM_B>>>(
        (const __half*)pAH, (const __half*)pw1T, (const __half*)pvgT,
        (__half*)pHh, sortedp, offsp);

    // down projection (gathered, K=3072) -> fp16; 64-row tiles for grid occupancy
    gemm_h64<<<dim3(6, 32, 8), 256, SM_B64>>>(
        (const __half*)pHh, DD, FF, sW2, sortedp, offsp);

    // final output projection (dense) -> fp32 d_out; 64-row tiles
    gemm_h64<<<dim3(6, 32, 1), 256, SM_B64>>>(
        (const __half*)pYh, DD, DD, sOW, sortedp, offsp);
}

// round 17
// speedup vs baseline: 1.7653x; 1.2214x over previous
#include <cuda_runtime.h>
#include <cuda_fp16.h>
#include <math.h>
#include <stdint.h>

// ---------------- problem constants ----------------
#define DD    768
#define FF    3072
#define NE    8
#define NB    2
#define NL    1024
#define NTOK  2048
#define NH    12
#define HD    64
#define WINW  128
#define NOUT  (NTOK*DD)

// ---------------- device scratch ----------------
__device__ __half g_K[NE*NTOK*DD];
__device__ __half g_V[NE*NTOK*DD];
__device__ float  g_Q[NTOK*DD];
__device__ __half g_xh[NTOK*DD];
__device__ __half g_attnh[NTOK*DD];
__device__ __half g_Hh[NTOK*FF];
__device__ __half g_Yh[NTOK*DD];
__device__ float  g_xpart[64*DD];         // xbar stage-1 partials [b*32+c][d]
__device__ float  g_xbar[NB*DD];
__device__ float  g_kbar[NE*NB*DD];
__device__ int    g_idx[NTOK];
__device__ int    g_sorted[NTOK];
__device__ int    g_counts[NE];
__device__ int    g_cursor[NE];
__device__ int    g_offs[NE+1];
__device__ float  g_Psum[NE];
// transposed fp16 weights [N][K] per expert
__device__ __half g_qT[NE*DD*DD];
__device__ __half g_kT[NE*DD*DD];
__device__ __half g_vT[NE*DD*DD];
__device__ __half g_w1T[NE*DD*FF];
__device__ __half g_vgT[NE*DD*FF];
__device__ __half g_w2T[NE*FF*DD];
__device__ __half g_outT[DD*DD];

// ---------------- PTX helpers ----------------
__device__ __forceinline__ uint32_t smem_u32(const void* p) {
    uint32_t a;
    asm("{ .reg .u64 t; cvta.to.shared.u64 t, %1; cvt.u32.u64 %0, t; }" : "=r"(a) : "l"(p));
    return a;
}
__device__ __forceinline__ void cp16(uint32_t s, const void* g) {
    asm volatile("cp.async.cg.shared.global [%0], [%1], 16;" :: "r"(s), "l"(g) : "memory");
}
__device__ __forceinline__ void cp_commit() {
    asm volatile("cp.async.commit_group;" ::: "memory");
}
template<int N> __device__ __forceinline__ void cp_wait() {
    asm volatile("cp.async.wait_group %0;" :: "n"(N) : "memory");
}
__device__ __forceinline__ void mma16(float* c, const uint32_t* a, const uint32_t* b) {
    asm volatile("mma.sync.aligned.m16n8k16.row.col.f32.f16.f16.f32 "
        "{%0,%1,%2,%3}, {%4,%5,%6,%7}, {%8,%9}, {%0,%1,%2,%3};"
        : "+f"(c[0]), "+f"(c[1]), "+f"(c[2]), "+f"(c[3])
        : "r"(a[0]), "r"(a[1]), "r"(a[2]), "r"(a[3]), "r"(b[0]), "r"(b[1]));
}
__device__ __forceinline__ void ldsm4(uint32_t* r, uint32_t addr) {
    asm volatile("ldmatrix.sync.aligned.m8n8.x4.shared.b16 {%0,%1,%2,%3}, [%4];"
        : "=r"(r[0]), "=r"(r[1]), "=r"(r[2]), "=r"(r[3]) : "r"(addr));
}

// ---------------- fused pre-pass: x->fp16 convert | xbar stage-1 | counter init ----------------
__global__ __launch_bounds__(256) void pre_k(const float* __restrict__ x, __half* __restrict__ xh) {
    int bid = blockIdx.x;
    int tid = threadIdx.x;
    if (bid < (NTOK * DD) / 256) {
        int i = bid * 256 + tid;
        xh[i] = __float2half_rn(x[i]);
    } else if (bid < (NTOK * DD) / 256 + 64) {
        int q = bid - (NTOK * DD) / 256;       // q = b*32 + c
        int c = q & 31, b = q >> 5;
        const float* xb = x + ((size_t)b * NL + (size_t)c * 32) * DD;
        for (int d = tid; d < DD; d += 256) {
            float s = 0.f;
#pragma unroll 8
            for (int jj = 0; jj < 32; jj++) s += xb[(size_t)jj * DD + d];
            g_xpart[(size_t)q * DD + d] = s;
        }
    } else {
        if (tid < NE) { g_counts[tid] = 0; g_Psum[tid] = 0.f; }
    }
}

// ---------------- xbar stage-2: reduce 32 chunk partials (fixed order) ----------------
__global__ __launch_bounds__(256) void xbar2_k() {
    int tid = threadIdx.x;
    int d = blockIdx.x * 128 + (tid & 127);
    int b = tid >> 7;
    float s = 0.f;
#pragma unroll
    for (int c = 0; c < 32; c++) s += g_xpart[(size_t)(b * 32 + c) * DD + d];
    g_xbar[b * DD + d] = s * (1.f / (float)NL);
}

// ---------------- kbar[e,b,:] = xbar[b,:] @ k_w[e], parallel over (e, d-chunk) ----------------
__global__ __launch_bounds__(256) void kbar2_k(const float* __restrict__ k_w) {
    __shared__ float xs[NB * DD];
    int tid = threadIdx.x;
    for (int i = tid; i < NB * DD; i += 256) xs[i] = g_xbar[i];
    __syncthreads();
    int e = blockIdx.x;
    int d = blockIdx.y * 128 + (tid & 127);
    int b = tid >> 7;
    const float* W = k_w + (size_t)e * DD * DD;
    const float* xb = xs + b * DD;
    float a = 0.f;
    for (int dk = 0; dk < DD; dk++) a += xb[dk] * W[(size_t)dk * DD + d];
    g_kbar[(size_t)(e * NB + b) * DD + d] = a;
}

// ---------------- router ----------------
__global__ __launch_bounds__(256) void router_k(const float* __restrict__ x,
                                                const float* __restrict__ gw) {
    int gtid = blockIdx.x * 256 + threadIdx.x;
    int tok  = gtid >> 5;
    int lane = gtid & 31;
    if (tok >= NTOK) return;
    const float* xr = x + (size_t)tok * DD;
    float acc[NE];
#pragma unroll
    for (int e = 0; e < NE; e++) acc[e] = 0.f;
    for (int d = lane; d < DD; d += 32) {
        float xv = xr[d];
        const float* g = gw + (size_t)d * NE;
#pragma unroll
        for (int e = 0; e < NE; e++) acc[e] += xv * g[e];
    }
#pragma unroll
    for (int e = 0; e < NE; e++)
#pragma unroll
        for (int off = 16; off; off >>= 1)
            acc[e] += __shfl_xor_sync(0xffffffffu, acc[e], off);
    if (lane == 0) {
        float l[NE]; float mx = -1e30f;
#pragma unroll
        for (int e = 0; e < NE; e++) { l[e] = acc[e] * 0.5f; mx = fmaxf(mx, l[e]); }
        int best = 0; float bv = l[0];
#pragma unroll
        for (int e = 1; e < NE; e++) if (l[e] > bv) { bv = l[e]; best = e; }
        g_idx[tok] = best;
        atomicAdd(&g_counts[best], 1);
        float p[NE]; float se = 0.f;
#pragma unroll
        for (int e = 0; e < NE; e++) { p[e] = expf(l[e] - mx); se += p[e]; }
        float inv = 1.f / se;
#pragma unroll
        for (int e = 0; e < NE; e++) atomicAdd(&g_Psum[e], p[e] * inv);
    }
}

// ---------------- offsets + aux + scatter (one block) ----------------
__global__ __launch_bounds__(256) void offscatter_k(float* __restrict__ dout, long long out_size) {
    int tid = threadIdx.x;
    if (tid == 0) {
        int o = 0;
        for (int e = 0; e < NE; e++) { g_offs[e] = o; g_cursor[e] = o; o += g_counts[e]; }
        g_offs[NE] = o;
        float aux = 0.f;
        for (int e = 0; e < NE; e++) aux += (float)g_counts[e] * g_Psum[e];
        aux *= (float)NE / ((float)NTOK * (float)NTOK);
        if (out_size > (long long)NOUT) dout[NOUT] = aux;
    }
    __syncthreads();
    for (int t = tid; t < NTOK; t += 256) {
        int e = g_idx[t];
        int p = atomicAdd(&g_cursor[e], 1);
        g_sorted[p] = t;
    }
}

// ---------------- weight transpose + fp16 convert: src[e][K][N] -> dst[e][N][K] half ----------------
__global__ __launch_bounds__(256) void transposeh_k(
    const float* s0, const float* s1, const float* s2,
    __half* d0, __half* d1, __half* d2, int K, int N) {
    __shared__ float t[64][33];
    int which = blockIdx.z / NE, e = blockIdx.z % NE;
    const float* sb = (which == 0) ? s0 : (which == 1) ? s1 : s2;
    __half* db = (which == 0) ? d0 : (which == 1) ? d1 : d2;
    const float* s = sb + (size_t)e * K * N;
    __half* d = db + (size_t)e * K * N;
    int n0 = blockIdx.x * 32, k0 = blockIdx.y * 64;
    int tx = threadIdx.x, ty = threadIdx.y;
#pragma unroll
    for (int i = 0; i < 64; i += 8)
        t[ty + i][tx] = s[(size_t)(k0 + ty + i) * N + n0 + tx];
    __syncthreads();
#pragma unroll
    for (int i = 0; i < 32; i += 8) {
        int r = ty + i;
        __half2 h = __floats2half2_rn(t[2 * tx][r], t[2 * tx + 1][r]);
        *(__half2*)(d + (size_t)(n0 + r) * K + k0 + 2 * tx) = h;
    }
}

// ---------------- slot descriptor ----------------
struct SlotH {
    const __half* B;
    void* C;
    unsigned long long strideB;
    unsigned long long strideC;
    int gather;
    int outh;
};

// ---------------- fp16 mma.sync GEMM (m16n8k16), single-B, 128x128 ----------------
#define STG_A  10240
#define STG_AB 20480
__global__ __launch_bounds__(256, 2) void gemm_h(
    const __half* __restrict__ A, int ldc, int K, int nbx,
    SlotH s0, SlotH s1, SlotH s2,
    const int* __restrict__ sorted, const int* __restrict__ offs)
{
    extern __shared__ char smc[];
    __shared__ int rs[128];
    int which = blockIdx.x / nbx;
    int n0 = (blockIdx.x - which * nbx) * 128;
    const __half* Bb; void* Cb; unsigned long long sB, sC; int gat, outh;
    if (which == 0)      { Bb = s0.B; Cb = s0.C; sB = s0.strideB; sC = s0.strideC; gat = s0.gather; outh = s0.outh; }
    else if (which == 1) { Bb = s1.B; Cb = s1.C; sB = s1.strideB; sC = s1.strideC; gat = s1.gather; outh = s1.outh; }
    else                 { Bb = s2.B; Cb = s2.C; sB = s2.strideB; sC = s2.strideC; gat = s2.gather; outh = s2.outh; }
    int e = blockIdx.z;
    int cnt; const int* rmap;
    if (gat) { int st0 = offs[e]; cnt = offs[e + 1] - st0; rmap = sorted + st0; }
    else     { cnt = NTOK; rmap = nullptr; }
    int m0 = blockIdx.y * 128;
    if (m0 >= cnt) return;
    const __half* Be = Bb + sB * (size_t)e;

    int tid = threadIdx.x;
    if (tid < 128) {
        int ra = m0 + tid;
        int row = (ra < cnt) ? ra : (cnt - 1);
        rs[tid] = rmap ? rmap[row] : row;
    }
    __syncthreads();

    uint32_t sbase = smem_u32(smc);

    const __half* aptr[2]; const __half* bptr[2];
    uint32_t soA[2], soB[2];
#pragma unroll
    for (int i = 0; i < 2; i++) {
        int f = i * 256 + tid;
        int row = f >> 2, c = f & 3;
        aptr[i] = A + (size_t)rs[row] * K + c * 8;
        bptr[i] = Be + (size_t)(n0 + row) * K + c * 8;
        uint32_t so = (uint32_t)(row * 80 + c * 16);
        soA[i] = sbase + so;
        soB[i] = sbase + (uint32_t)STG_A + so;
    }

    int lane = tid & 31, wid = tid >> 5;
    int g = lane >> 2, t4 = lane & 3;
    int wm = wid & 1, wn = wid >> 1;
    int mb0 = wm * 64, nb0 = wn * 32;
    int lr = lane & 7, lg = lane >> 3;

    float c1[4][4][4];
#pragma unroll
    for (int mf = 0; mf < 4; mf++)
#pragma unroll
        for (int nf = 0; nf < 4; nf++)
#pragma unroll
            for (int q = 0; q < 4; q++) c1[mf][nf][q] = 0.f;

    int NIT = K >> 5;

    auto load_tile = [&](int it, int st) {
        uint32_t sb = (uint32_t)st * STG_AB;
        int k0 = it << 5;
#pragma unroll
        for (int i = 0; i < 2; i++) cp16(soA[i] + sb, aptr[i] + k0);
#pragma unroll
        for (int i = 0; i < 2; i++) cp16(soB[i] + sb, bptr[i] + k0);
        cp_commit();
    };

    load_tile(0, 0);
    load_tile(1, 1);
    load_tile(2, 2);

    uint32_t aRowOff = (uint32_t)((lr + (lg & 1) * 8) * 80 + (lg >> 1) * 16);
    uint32_t bRowOff = (uint32_t)((lr + (lg >> 1) * 8) * 80 + (lg & 1) * 16);

    for (int it = 0; it < NIT; it++) {
        int rem = NIT - 1 - it;
        if (rem >= 2) cp_wait<2>(); else if (rem == 1) cp_wait<1>(); else cp_wait<0>();
        __syncthreads();
        int st = it & 3;
        uint32_t Ast = sbase + (uint32_t)st * STG_AB;
        uint32_t Bst = Ast + (uint32_t)STG_A;

#pragma unroll
        for (int kk = 0; kk < 32; kk += 16) {
            uint32_t kbyte = (uint32_t)(kk * 2);
            uint32_t af[4][4];
#pragma unroll
            for (int mf = 0; mf < 4; mf++)
                ldsm4(af[mf], Ast + (uint32_t)((mb0 + mf * 16) * 80) + aRowOff + kbyte);
            uint32_t bf[2][4];
#pragma unroll
            for (int np = 0; np < 2; np++)
                ldsm4(bf[np], Bst + (uint32_t)((nb0 + np * 16) * 80) + bRowOff + kbyte);
#pragma unroll
            for (int mf = 0; mf < 4; mf++)
#pragma unroll
                for (int nf = 0; nf < 4; nf++)
                    mma16(c1[mf][nf], af[mf], &bf[nf >> 1][(nf & 1) * 2]);
        }
        if (it + 3 < NIT) load_tile(it + 3, (it + 3) & 3);
    }

#pragma unroll
    for (int mf = 0; mf < 4; mf++) {
        int lr0 = mb0 + mf * 16 + g;
        int lr1 = lr0 + 8;
        bool v0 = (m0 + lr0) < cnt;
        bool v1 = (m0 + lr1) < cnt;
        size_t o0 = (size_t)rs[lr0] * ldc + n0 + nb0;
        size_t o1 = (size_t)rs[lr1] * ldc + n0 + nb0;
#pragma unroll
        for (int nf = 0; nf < 4; nf++) {
            int co = nf * 8 + 2 * t4;
            float a0 = c1[mf][nf][0], a1 = c1[mf][nf][1];
            float a2 = c1[mf][nf][2], a3 = c1[mf][nf][3];
            if (outh) {
                __half* C = (__half*)Cb + sC * (size_t)e;
                if (v0) *(__half2*)(C + o0 + co) = __floats2half2_rn(a0, a1);
                if (v1) *(__half2*)(C + o1 + co) = __floats2half2_rn(a2, a3);
            } else {
                float* C = (float*)Cb + sC * (size_t)e;
                if (v0) *(float2*)(C + o0 + co) = make_float2(a0, a1);
                if (v1) *(float2*)(C + o1 + co) = make_float2(a2, a3);
            }
        }
    }
}

// ---------------- fp16 GEMM, block tile 64x128x32 (tail GEMMs) ----------------
#define STG64_A  5120
#define STG64_AB 15360
__global__ __launch_bounds__(256, 2) void gemm_h64(
    const __half* __restrict__ A, int ldc, int K,
    SlotH s0,
    const int* __restrict__ sorted, const int* __restrict__ offs)
{
    extern __shared__ char smc[];
    __shared__ int rs[64];
    int n0 = blockIdx.x * 128;
    const __half* Bb = s0.B; void* Cb = s0.C;
    unsigned long long sB = s0.strideB, sC = s0.strideC;
    int gat = s0.gather, outh = s0.outh;
    int e = blockIdx.z;
    int cnt; const int* rmap;
    if (gat) { int st0 = offs[e]; cnt = offs[e + 1] - st0; rmap = sorted + st0; }
    else     { cnt = NTOK; rmap = nullptr; }
    int m0 = blockIdx.y * 64;
    if (m0 >= cnt) return;
    const __half* Be = Bb + sB * (size_t)e;

    int tid = threadIdx.x;
    if (tid < 64) {
        int ra = m0 + tid;
        int row = (ra < cnt) ? ra : (cnt - 1);
        rs[tid] = rmap ? rmap[row] : row;
    }
    __syncthreads();

    uint32_t sbase = smem_u32(smc);

    const __half* aptr; const __half* bptr[2];
    uint32_t soA, soB[2];
    {
        int row = tid >> 2, c = tid & 3;
        aptr = A + (size_t)rs[row] * K + c * 8;
        soA  = sbase + (uint32_t)(row * 80 + c * 16);
    }
#pragma unroll
    for (int i = 0; i < 2; i++) {
        int f = i * 256 + tid;
        int row = f >> 2, c = f & 3;
        bptr[i] = Be + (size_t)(n0 + row) * K + c * 8;
        soB[i]  = sbase + (uint32_t)STG64_A + (uint32_t)(row * 80 + c * 16);
    }

    int lane = tid & 31, wid = tid >> 5;
    int g = lane >> 2, t4 = lane & 3;
    int nb0 = wid * 16;
    int lr = lane & 7, lg = lane >> 3;

    float c1[4][2][4];
#pragma unroll
    for (int mf = 0; mf < 4; mf++)
#pragma unroll
        for (int nf = 0; nf < 2; nf++)
#pragma unroll
            for (int q = 0; q < 4; q++) c1[mf][nf][q] = 0.f;

    int NIT = K >> 5;

    auto load_tile = [&](int it, int st) {
        uint32_t sb = (uint32_t)st * STG64_AB;
        int k0 = it << 5;
        cp16(soA + sb, aptr + k0);
#pragma unroll
        for (int i = 0; i < 2; i++) cp16(soB[i] + sb, bptr[i] + k0);
        cp_commit();
    };

    load_tile(0, 0);
    load_tile(1, 1);
    load_tile(2, 2);

    uint32_t aRowOff = (uint32_t)((lr + (lg & 1) * 8) * 80 + (lg >> 1) * 16);
    uint32_t bRowOff = (uint32_t)((lr + (lg >> 1) * 8) * 80 + (lg & 1) * 16);

    for (int it = 0; it < NIT; it++) {
        int rem = NIT - 1 - it;
        if (rem >= 2) cp_wait<2>(); else if (rem == 1) cp_wait<1>(); else cp_wait<0>();
        __syncthreads();
        int st = it & 3;
        uint32_t Ast = sbase + (uint32_t)st * STG64_AB;
        uint32_t Bst = Ast + (uint32_t)STG64_A;

#pragma unroll
        for (int kk = 0; kk < 32; kk += 16) {
            uint32_t kbyte = (uint32_t)(kk * 2);
            uint32_t af[4][4];
#pragma unroll
            for (int mf = 0; mf < 4; mf++)
                ldsm4(af[mf], Ast + (uint32_t)((mf * 16) * 80) + aRowOff + kbyte);
            uint32_t bf[4];
            ldsm4(bf, Bst + (uint32_t)(nb0 * 80) + bRowOff + kbyte);
#pragma unroll
            for (int mf = 0; mf < 4; mf++)
#pragma unroll
                for (int nf = 0; nf < 2; nf++)
                    mma16(c1[mf][nf], af[mf], &bf[nf * 2]);
        }
        if (it + 3 < NIT) load_tile(it + 3, (it + 3) & 3);
    }

#pragma unroll
    for (int mf = 0; mf < 4; mf++) {
        int lr0 = mf * 16 + g;
        int lr1 = lr0 + 8;
        bool v0 = (m0 + lr0) < cnt;
        bool v1 = (m0 + lr1) < cnt;
        size_t o0 = (size_t)rs[lr0] * ldc + n0 + nb0;
        size_t o1 = (size_t)rs[lr1] * ldc + n0 + nb0;
#pragma unroll
        for (int nf = 0; nf < 2; nf++) {
            int co = nf * 8 + 2 * t4;
            float a0 = c1[mf][nf][0], a1 = c1[mf][nf][1];
            float a2 = c1[mf][nf][2], a3 = c1[mf][nf][3];
            if (outh) {
                __half* C = (__half*)Cb + sC * (size_t)e;
                if (v0) *(__half2*)(C + o0 + co) = __floats2half2_rn(a0, a1);
                if (v1) *(__half2*)(C + o1 + co) = __floats2half2_rn(a2, a3);
            } else {
                float* C = (float*)Cb + sC * (size_t)e;
                if (v0) *(float2*)(C + o0 + co) = make_float2(a0, a1);
                if (v1) *(float2*)(C + o1 + co) = make_float2(a2, a3);
            }
        }
    }
}

// ---------------- fused SwiGLU dual GEMM: h = silu(A@w1) * (A@vg) ----------------
#define STG_B2 5120
__global__ __launch_bounds__(256, 2) void gemm_swiglu(
    const __half* __restrict__ A,
    const __half* __restrict__ W1, const __half* __restrict__ VG,
    __half* __restrict__ C,
    const int* __restrict__ sorted, const int* __restrict__ offs)
{
    extern __shared__ char smc[];
    __shared__ int rs[128];
    const int K = DD, ldc = FF;
    int n0 = blockIdx.x * 64;
    int e = blockIdx.z;
    int st0 = offs[e];
    int cnt = offs[e + 1] - st0;
    const int* rmap = g_sorted + st0;
    int m0 = blockIdx.y * 128;
    if (m0 >= cnt) return;
    const __half* B1e = W1 + (size_t)e * DD * FF;
    const __half* B2e = VG + (size_t)e * DD * FF;

    int tid = threadIdx.x;
    if (tid < 128) {
        int ra = m0 + tid;
        int row = (ra < cnt) ? ra : (cnt - 1);
        rs[tid] = rmap ? rmap[row] : row;
    }
    __syncthreads();

    uint32_t sbase = smem_u32(smc);

    const __half* aptr[2]; const __half* b1p; const __half* b2p;
    uint32_t soA[2], soB;
#pragma unroll
    for (int i = 0; i < 2; i++) {
        int f = i * 256 + tid;
        int row = f >> 2, c = f & 3;
        aptr[i] = A + (size_t)rs[row] * K + c * 8;
        soA[i]  = sbase + (uint32_t)(row * 80 + c * 16);
    }
    {
        int row = tid >> 2, c = tid & 3;
        b1p = B1e + (size_t)(n0 + row) * K + c * 8;
        b2p = B2e + (size_t)(n0 + row) * K + c * 8;
        soB = sbase + (uint32_t)STG_A + (uint32_t)(row * 80 + c * 16);
    }

    int lane = tid & 31, wid = tid >> 5;
    int g = lane >> 2, t4 = lane & 3;
    int wm = wid & 1, wn = wid >> 1;
    int mb0 = wm * 64, nb0 = wn * 16;
    int lr = lane & 7, lg = lane >> 3;

    float c1[4][2][4], c2[4][2][4];
#pragma unroll
    for (int mf = 0; mf < 4; mf++)
#pragma unroll
        for (int nf = 0; nf < 2; nf++)
#pragma unroll
            for (int q = 0; q < 4; q++) { c1[mf][nf][q] = 0.f; c2[mf][nf][q] = 0.f; }

    int NIT = K >> 5;

    auto load_tile = [&](int it, int st) {
        uint32_t sb = (uint32_t)st * STG_AB;
        int k0 = it << 5;
#pragma unroll
        for (int i = 0; i < 2; i++) cp16(soA[i] + sb, aptr[i] + k0);
        cp16(soB + sb, b1p + k0);
        cp16(soB + sb + (uint32_t)STG_B2, b2p + k0);
        cp_commit();
    };

    load_tile(0, 0);
    load_tile(1, 1);
    load_tile(2, 2);

    uint32_t aRowOff = (uint32_t)((lr + (lg & 1) * 8) * 80 + (lg >> 1) * 16);
    uint32_t bRowOff = (uint32_t)((lr + (lg >> 1) * 8) * 80 + (lg & 1) * 16);

    for (int it = 0; it < NIT; it++) {
        int rem = NIT - 1 - it;
        if (rem >= 2) cp_wait<2>(); else if (rem == 1) cp_wait<1>(); else cp_wait<0>();
        __syncthreads();
        int st = it & 3;
        uint32_t Ast = sbase + (uint32_t)st * STG_AB;
        uint32_t B1st = Ast + (uint32_t)STG_A;
        uint32_t B2st = B1st + (uint32_t)STG_B2;

#pragma unroll
        for (int kk = 0; kk < 32; kk += 16) {
            uint32_t kbyte = (uint32_t)(kk * 2);
            uint32_t af[4][4];
#pragma unroll
            for (int mf = 0; mf < 4; mf++)
                ldsm4(af[mf], Ast + (uint32_t)((mb0 + mf * 16) * 80) + aRowOff + kbyte);
            uint32_t b1f[4], b2f[4];
            ldsm4(b1f, B1st + (uint32_t)(nb0 * 80) + bRowOff + kbyte);
            ldsm4(b2f, B2st + (uint32_t)(nb0 * 80) + bRowOff + kbyte);
#pragma unroll
            for (int mf = 0; mf < 4; mf++)
#pragma unroll
                for (int nf = 0; nf < 2; nf++) {
                    mma16(c1[mf][nf], af[mf], &b1f[nf * 2]);
                    mma16(c2[mf][nf], af[mf], &b2f[nf * 2]);
                }
        }
        if (it + 3 < NIT) load_tile(it + 3, (it + 3) & 3);
    }

#pragma unroll
    for (int mf = 0; mf < 4; mf++) {
        int lr0 = mb0 + mf * 16 + g;
        int lr1 = lr0 + 8;
        bool v0 = (m0 + lr0) < cnt;
        bool v1 = (m0 + lr1) < cnt;
        __half* p0 = C + (size_t)rs[lr0] * ldc + n0 + nb0;
        __half* p1 = C + (size_t)rs[lr1] * ldc + n0 + nb0;
#pragma unroll
        for (int nf = 0; nf < 2; nf++) {
            int co = nf * 8 + 2 * t4;
            float z0 = c1[mf][nf][0], z1 = c1[mf][nf][1];
            float z2 = c1[mf][nf][2], z3 = c1[mf][nf][3];
            float h0 = z0 / (1.f + expf(-z0)) * c2[mf][nf][0];
            float h1 = z1 / (1.f + expf(-z1)) * c2[mf][nf][1];
            float h2 = z2 / (1.f + expf(-z2)) * c2[mf][nf][2];
            float h3 = z3 / (1.f + expf(-z3)) * c2[mf][nf][3];
            if (v0) *(__half2*)(p0 + co) = __floats2half2_rn(h0, h1);
            if (v1) *(__half2*)(p1 + co) = __floats2half2_rn(h2, h3);
        }
    }
}

// ---------------- sliding-window attention with Reynolds modulation ----------------
#define KHPAD 776
__global__ __launch_bounds__(384) void attn_k() {
    int token = blockIdx.x;
    int b = token >> 10;
    int t = token & (NL - 1);
    int e = g_idx[token];

    __shared__ float qs[DD];
    __shared__ float sc[NH][WINW + 4];
    __shared__ float mh[NH], invs[NH];
    __shared__ __half ks[16][KHPAD];

    int tid = threadIdx.x, lane = tid & 31, h = tid >> 5;
    for (int d = tid; d < DD; d += 384) qs[d] = g_Q[(size_t)token * DD + d];
    __syncthreads();

    int jlo = (t >= WINW - 1) ? t - (WINW - 1) : 0;
    int nj  = t - jlo + 1;
    size_t ebbase = (size_t)(e * NB + b) * NL * DD;
    const __half* Kb = g_K + ebbase;

    {
        const float* kb = g_kbar + (size_t)(e * NB + b) * DD + h*64 + lane*2;
        float q0 = qs[h*64 + lane*2], q1 = qs[h*64 + lane*2 + 1];
        float p = q0 * kb[0] + q1 * kb[1];
#pragma unroll
        for (int off = 16; off; off >>= 1) p += __shfl_xor_sync(0xffffffffu, p, off);
        if (lane == 0) mh[h] = p * 0.125f;
    }

    int j2 = lane >> 1, half = lane & 1;
    const float* qr = &qs[h*64 + half*32];
    int ntile = (nj + 15) >> 4;
    for (int tt = 0; tt < ntile; tt++) {
        int j0 = tt << 4;
        int rows = nj - j0; if (rows > 16) rows = 16;
        for (int v = tid; v < rows * 96; v += 384) {
            int r = v / 96, c8 = v % 96;
            *(float4*)&ks[r][c8 * 8] = *(const float4*)(Kb + (size_t)(jlo + j0 + r) * DD + c8 * 8);
        }
        __syncthreads();
        const __half2* k2 = (const __half2*)&ks[j2][h*64 + half*32];
        float s = 0.f;
#pragma unroll
        for (int i = 0; i < 16; i++) {
            float2 kf = __half22float2(k2[i]);
            s += qr[2*i] * kf.x + qr[2*i+1] * kf.y;
        }
        s += __shfl_xor_sync(0xffffffffu, s, 1);
        if (half == 0 && j2 < rows) sc[h][j0 + j2] = s * 0.125f;
        __syncthreads();
    }

    float m = mh[h];
    float mx = -1e30f;
    for (int jj = lane; jj < nj; jj += 32) {
        float sv = sc[h][jj];
        float sig = 1.f / (1.f + __expf(-sv));
        float sp = sv + 0.1f * sv - 0.1f * sig * sig - 0.1f * fabsf(sv - m);
        sc[h][jj] = sp;
        mx = fmaxf(mx, sp);
    }
#pragma unroll
    for (int off = 16; off; off >>= 1) mx = fmaxf(mx, __shfl_xor_sync(0xffffffffu, mx, off));
    float sum = 0.f;
    for (int jj = lane; jj < nj; jj += 32) {
        float pexp = __expf(sc[h][jj] - mx);
        sc[h][jj] = pexp;
        sum += pexp;
    }
#pragma unroll
    for (int off = 16; off; off >>= 1) sum += __shfl_xor_sync(0xffffffffu, sum, off);
    if (lane == 0) invs[h] = 1.f / sum;
    __syncthreads();

    const __half* Vb = g_V + ebbase;
    for (int od = tid; od < DD; od += 384) {
        int hh = od >> 6;
        const __half* vb = Vb + (size_t)jlo * DD + od;
        float a0 = 0.f, a1 = 0.f, a2 = 0.f, a3 = 0.f;
        int j = 0;
        for (; j + 4 <= nj; j += 4) {
            a0 += sc[hh][j+0] * __half2float(vb[(size_t)(j+0)*DD]);
            a1 += sc[hh][j+1] * __half2float(vb[(size_t)(j+1)*DD]);
            a2 += sc[hh][j+2] * __half2float(vb[(size_t)(j+2)*DD]);
            a3 += sc[hh][j+3] * __half2float(vb[(size_t)(j+3)*DD]);
        }
        for (; j < nj; j++) a0 += sc[hh][j] * __half2float(vb[(size_t)j*DD]);
        g_attnh[(size_t)token * DD + od] = __float2half_rn((a0 + a1 + a2 + a3) * invs[hh]);
    }
}

// ---------------- launch ----------------
extern "C" void kernel_launch(void* const* d_in, const int* in_sizes, int n_in,
                              void* d_out, int out_size) {
    const float* x      = (const float*)d_in[0];
    const float* gate_w = (const float*)d_in[1];
    const float* q_w    = (const float*)d_in[2];
    const float* k_w    = (const float*)d_in[3];
    const float* v_w    = (const float*)d_in[4];
    const float* w1     = (const float*)d_in[5];
    const float* vg     = (const float*)d_in[6];
    const float* w2     = (const float*)d_in[7];
    const float* out_w  = (const float*)d_in[8];
    float* out = (float*)d_out;

    void *pK, *pV, *pQ, *pXH, *pAH, *pHh, *pYh, *pS, *pO;
    void *pqT, *pkT, *pvT, *pw1T, *pvgT, *pw2T, *poT;
    cudaGetSymbolAddress(&pK, g_K);
    cudaGetSymbolAddress(&pV, g_V);
    cudaGetSymbolAddress(&pQ, g_Q);
    cudaGetSymbolAddress(&pXH, g_xh);
    cudaGetSymbolAddress(&pAH, g_attnh);
    cudaGetSymbolAddress(&pHh, g_Hh);
    cudaGetSymbolAddress(&pYh, g_Yh);
    cudaGetSymbolAddress(&pS, g_sorted);
    cudaGetSymbolAddress(&pO, g_offs);
    cudaGetSymbolAddress(&pqT, g_qT);
    cudaGetSymbolAddress(&pkT, g_kT);
    cudaGetSymbolAddress(&pvT, g_vT);
    cudaGetSymbolAddress(&pw1T, g_w1T);
    cudaGetSymbolAddress(&pvgT, g_vgT);
    cudaGetSymbolAddress(&pw2T, g_w2T);
    cudaGetSymbolAddress(&poT, g_outT);
    const int* sortedp = (const int*)pS;
    const int* offsp   = (const int*)pO;

    const int SM_B   = 4 * STG_AB;    // 81920 B
    const int SM_B64 = 4 * STG64_AB;  // 61440 B
    cudaFuncSetAttribute(gemm_h,      cudaFuncAttributeMaxDynamicSharedMemorySize, SM_B);
    cudaFuncSetAttribute(gemm_h64,    cudaFuncAttributeMaxDynamicSharedMemorySize, SM_B64);
    cudaFuncSetAttribute(gemm_swiglu, cudaFuncAttributeMaxDynamicSharedMemorySize, SM_B);

    // weight transposes + fp16 convert -> [N][K]
    transposeh_k<<<dim3(24, 12, 3 * NE), dim3(32, 8)>>>(
        q_w, k_w, v_w, (__half*)pqT, (__half*)pkT, (__half*)pvT, DD, DD);
    transposeh_k<<<dim3(96, 12, 2 * NE), dim3(32, 8)>>>(
        w1, vg, nullptr, (__half*)pw1T, (__half*)pvgT, nullptr, DD, FF);
    transposeh_k<<<dim3(24, 48, NE), dim3(32, 8)>>>(
        w2, nullptr, nullptr, (__half*)pw2T, nullptr, nullptr, FF, DD);
    transposeh_k<<<dim3(24, 12, 1), dim3(32, 8)>>>(
        out_w, nullptr, nullptr, (__half*)poT, nullptr, nullptr, DD, DD);

    // fused pre-pass: xconv (6144 blocks) + xbar stage-1 (64) + init (1)
    pre_k<<<(NTOK * DD) / 256 + 64 + 1, 256>>>(x, (__half*)pXH);
    router_k<<<NTOK / 8, 256>>>(x, gate_w);
    offscatter_k<<<1, 256>>>(out, (long long)out_size);
    xbar2_k<<<6, 256>>>();
    kbar2_k<<<dim3(NE, 6), 256>>>(k_w);

    SlotH sK  = { (const __half*)pkT,  pK,  (unsigned long long)DD*DD, (unsigned long long)NTOK*DD, 0, 1 };
    SlotH sV  = { (const __half*)pvT,  pV,  (unsigned long long)DD*DD, (unsigned long long)NTOK*DD, 0, 1 };
    SlotH sQ  = { (const __half*)pqT,  pQ,  (unsigned long long)DD*DD, 0ull, 1, 0 };
    SlotH sW2 = { (const __half*)pw2T, pYh, (unsigned long long)FF*DD, 0ull, 1, 1 };
    SlotH sOW = { (const __half*)poT,  d_out, 0ull, 0ull, 0, 0 };

    // K, V (dense, fp16 out) + Q (gathered, fp32 out) in one launch
    gemm_h<<<dim3(18, 16, 8), 256, SM_B>>>(
        (const __half*)pXH, DD, DD, 6, sK, sV, sQ, sortedp, offsp);

    attn_k<<<NTOK, 384>>>();

    // fused SwiGLU dual GEMM -> fp16
    gemm_swiglu<<<dim3(FF/64, 16, 8), 256, SM_B>>>(
        (const __half*)pAH, (const __half*)pw1T, (const __half*)pvgT,
        (__half*)pHh, sortedp, offsp);

    // down projection (gathered, K=3072) -> fp16; 64-row tiles
    gemm_h64<<<dim3(6, 32, 8), 256, SM_B64>>>(
        (const __half*)pHh, DD, FF, sW2, sortedp, offsp);

    // final output projection (dense) -> fp32 d_out; 64-row tiles
    gemm_h64<<<dim3(6, 32, 1), 256, SM_B64>>>(
        (const __half*)pYh, DD, DD, sOW, sortedp, offsp);
}